// round 3
// baseline (speedup 1.0000x reference)
#include <cuda_runtime.h>

// Problem constants
#define BB 2
#define C0 512
#define CT 1024        // total channels
#define TT 1024        // time
#define HW 49          // 7*7
#define DD 128         // SIM_DIM / OUT_DIM
#define LL 101         // LOOKUP
#define W2 50

// Scratch (device globals: allowed; no runtime allocation)
__device__ float g_feats[BB * CT * TT];          // [b][c][t]  8 MB
__device__ float g_xpart[4][BB * TT * DD];       // 4 k-split partials, 4 MB
__device__ float g_xnorm[BB * TT * DD];          // normalized rows, 1 MB
__device__ float g_band[BB * TT * LL];           // banded sims, 827 KB

// ---------------------------------------------------------------------------
// K1: spatial mean pool.  warp handles (b, c, 32 consecutive t).
// Region = 32*49 = 1568 floats contiguous -> 392 float4, fully coalesced.
// Transpose via smem (stride 49 is odd -> conflict-free reads), write feats
// [b][c][t] coalesced along t.
// ---------------------------------------------------------------------------
__global__ void __launch_bounds__(128) pool_kernel(const float* __restrict__ x0,
                                                   const float* __restrict__ x1) {
    __shared__ float sm[4][1568];
    const int w = threadIdx.x >> 5;
    const int lane = threadIdx.x & 31;
    const unsigned wid = blockIdx.x * 4u + w;
    const int tchunk = wid & 31;          // which 32-t chunk
    const int c = (wid >> 5) & 1023;      // channel 0..1023
    const int b = wid >> 15;              // batch

    const float* src = (c < C0)
        ? x0 + ((size_t)((b * C0 + c) * TT) + tchunk * 32) * HW
        : x1 + ((size_t)((b * C0 + (c - C0)) * TT) + tchunk * 32) * HW;

    const float4* s4 = (const float4*)src;   // 16B-aligned: offset multiple of 1568 floats
    float4* d4 = (float4*)sm[w];
#pragma unroll
    for (int i = 0; i < 12; i++) d4[i * 32 + lane] = s4[i * 32 + lane];
    if (lane < 8) d4[384 + lane] = s4[384 + lane];
    __syncwarp();

    const float* row = &sm[w][lane * 49];
    float s = 0.f;
#pragma unroll
    for (int j = 0; j < 49; j++) s += row[j];
    g_feats[((b << 10) + c) * TT + tchunk * 32 + lane] = s * (1.0f / 49.0f);
}

// ---------------------------------------------------------------------------
// K2: projection GEMM.  x[b,t,d] = sum_c feats[b,c,t] * proj_w[c,d]
// feats is already K-major ([c][t]) = ideal "A^T" smem layout.
// Tile: M=32 (t), N=128 (d), K split 4x256 across blockIdx.y -> 256 blocks.
// Thread computes 4x4 outputs. Partials to g_xpart (deterministic, no atomics).
// ---------------------------------------------------------------------------
__global__ void __launch_bounds__(256) gemm_proj_kernel(const float* __restrict__ proj_w) {
    __shared__ float As[16][32];
    __shared__ float Bs[16][128];
    const int tid = threadIdx.x;
    const int gm0 = blockIdx.x * 32;          // global row (b*T+t), 0..2047
    const int b = gm0 >> 10;
    const int t0 = gm0 & 1023;
    const int ks = blockIdx.y;
    const int k0base = ks * 256;
    const int tm = tid >> 5;                  // 0..7 -> 4 rows each
    const int tn = tid & 31;                  // 0..31 -> 4 cols each

    float acc[4][4];
#pragma unroll
    for (int i = 0; i < 4; i++)
#pragma unroll
        for (int j = 0; j < 4; j++) acc[i][j] = 0.f;

    const float4* p4 = (const float4*)proj_w;

    for (int kt = 0; kt < 256; kt += 16) {
        const int k0 = k0base + kt;
#pragma unroll
        for (int r = 0; r < 2; r++) {
            int idx = tid + r * 256;
            int kk = idx >> 5, mm = idx & 31;
            As[kk][mm] = g_feats[((b << 10) + k0 + kk) * TT + t0 + mm];
        }
#pragma unroll
        for (int r = 0; r < 2; r++) {
            int idx = tid + r * 256;
            int kk = idx >> 5, dq = idx & 31;
            ((float4*)Bs[kk])[dq] = p4[(k0 + kk) * 32 + dq];
        }
        __syncthreads();
#pragma unroll
        for (int kk = 0; kk < 16; kk++) {
            float4 a4 = *(const float4*)&As[kk][tm * 4];
            float4 b4 = *(const float4*)&Bs[kk][tn * 4];
            float a[4] = {a4.x, a4.y, a4.z, a4.w};
            float bv[4] = {b4.x, b4.y, b4.z, b4.w};
#pragma unroll
            for (int i = 0; i < 4; i++)
#pragma unroll
                for (int j = 0; j < 4; j++) acc[i][j] += a[i] * bv[j];
        }
        __syncthreads();
    }
#pragma unroll
    for (int i = 0; i < 4; i++) {
        float4 o = make_float4(acc[i][0], acc[i][1], acc[i][2], acc[i][3]);
        *(float4*)&g_xpart[ks][(gm0 + tm * 4 + i) * DD + tn * 4] = o;
    }
}

// ---------------------------------------------------------------------------
// K3: sum the 4 k-split partials, L2-normalize each 128-dim row.
// One warp per row (lane owns a float4 = 4 dims).
// ---------------------------------------------------------------------------
__global__ void __launch_bounds__(128) norm_kernel() {
    const int row = blockIdx.x * 4 + (threadIdx.x >> 5);   // 0..2047
    const int lane = threadIdx.x & 31;
    float4 v = make_float4(0.f, 0.f, 0.f, 0.f);
#pragma unroll
    for (int s = 0; s < 4; s++) {
        float4 p = ((const float4*)g_xpart[s])[row * 32 + lane];
        v.x += p.x; v.y += p.y; v.z += p.z; v.w += p.w;
    }
    float sq = v.x * v.x + v.y * v.y + v.z * v.z + v.w * v.w;
#pragma unroll
    for (int o = 16; o; o >>= 1) sq += __shfl_xor_sync(0xFFFFFFFFu, sq, o);
    const float inv = 1.0f / fmaxf(sqrtf(sq), 1e-12f);
    ((float4*)g_xnorm)[row * 32 + lane] =
        make_float4(v.x * inv, v.y * inv, v.z * inv, v.w * inv);
}

// ---------------------------------------------------------------------------
// K4: banded cosine similarity.  Block handles 16 t's; stages the 116 rows
// [t0-50, t0+65] in smem (two 64-dim half passes, padded rows -> conflict-free),
// each thread accumulates 7 j's for one t_local.
// ---------------------------------------------------------------------------
__global__ void __launch_bounds__(256) band_kernel() {
    __shared__ float4 xs[116 * 17];       // 116 rows x (16 float4 + 1 pad)
    const int tid = threadIdx.x;
    const int gt0 = blockIdx.x * 16;      // global row base
    const int b = gt0 >> 10;
    const int t0 = gt0 & 1023;
    const int tl = tid >> 4;              // t_local 0..15
    const int tj = tid & 15;              // j residue 0..15

    float accs[7] = {0.f, 0.f, 0.f, 0.f, 0.f, 0.f, 0.f};

    for (int p = 0; p < 2; p++) {
        __syncthreads();
#pragma unroll
        for (int i = 0; i < 8; i++) {
            int idx = tid + i * 256;
            if (idx < 116 * 16) {
                int r = idx >> 4, kq = idx & 15;
                int s = t0 - W2 + r;
                float4 v = make_float4(0.f, 0.f, 0.f, 0.f);
                if (s >= 0 && s < TT)
                    v = ((const float4*)g_xnorm)[((b << 10) + s) * 32 + p * 16 + kq];
                xs[r * 17 + kq] = v;
            }
        }
        __syncthreads();
#pragma unroll
        for (int k4 = 0; k4 < 16; k4++) {
            float4 a4 = xs[(tl + W2) * 17 + k4];
#pragma unroll
            for (int jj = 0; jj < 7; jj++) {
                int j = tj + jj * 16;
                if (j < LL) {
                    float4 b4 = xs[(tl + j) * 17 + k4];
                    accs[jj] += a4.x * b4.x + a4.y * b4.y + a4.z * b4.z + a4.w * b4.w;
                }
            }
        }
    }
#pragma unroll
    for (int jj = 0; jj < 7; jj++) {
        int j = tj + jj * 16;
        if (j < LL) g_band[(gt0 + tl) * LL + j] = accs[jj];
    }
}

// ---------------------------------------------------------------------------
// K5: out = relu(band @ fc_w + fc_b).  Block = 16 t rows x all 128 d.
// fc_w staged per 64-d half in padded smem; fused bias + relu to d_out.
// ---------------------------------------------------------------------------
__global__ void __launch_bounds__(256) fc_kernel(const float* __restrict__ fc_w,
                                                 const float* __restrict__ fc_b,
                                                 float* __restrict__ out) {
    __shared__ float As[16 * LL];         // 1616 floats, linear
    __shared__ float4 Bs[LL * 17];        // 101 rows x (16 float4 + pad)
    const int tid = threadIdx.x;
    const int gt0 = blockIdx.x * 16;      // global row base

#pragma unroll
    for (int i = 0; i < 7; i++) {
        int idx = tid + i * 256;
        if (idx < 16 * LL) As[idx] = g_band[gt0 * LL + idx];
    }

    const int tl = tid >> 4;              // t_local
    const int dg = tid & 15;              // d float4 group within half

    for (int h = 0; h < 2; h++) {
        __syncthreads();
#pragma unroll
        for (int i = 0; i < 7; i++) {
            int idx = tid + i * 256;
            if (idx < LL * 16) {
                int k = idx >> 4, q = idx & 15;
                Bs[k * 17 + q] = ((const float4*)fc_w)[k * 32 + h * 16 + q];
            }
        }
        __syncthreads();
        float4 acc = make_float4(0.f, 0.f, 0.f, 0.f);
        const float* arow = &As[tl * LL];
#pragma unroll 4
        for (int k = 0; k < LL; k++) {
            float a = arow[k];
            float4 b4 = Bs[k * 17 + dg];
            acc.x += a * b4.x; acc.y += a * b4.y;
            acc.z += a * b4.z; acc.w += a * b4.w;
        }
        float4 bias = ((const float4*)fc_b)[h * 16 + dg];
        acc.x = fmaxf(acc.x + bias.x, 0.f);
        acc.y = fmaxf(acc.y + bias.y, 0.f);
        acc.z = fmaxf(acc.z + bias.z, 0.f);
        acc.w = fmaxf(acc.w + bias.w, 0.f);
        ((float4*)out)[(gt0 + tl) * 32 + h * 16 + dg] = acc;
    }
}

// ---------------------------------------------------------------------------
extern "C" void kernel_launch(void* const* d_in, const int* in_sizes, int n_in,
                              void* d_out, int out_size) {
    const float* x0     = (const float*)d_in[0];
    const float* x1     = (const float*)d_in[1];
    const float* proj_w = (const float*)d_in[2];
    const float* fc_w   = (const float*)d_in[3];
    const float* fc_b   = (const float*)d_in[4];
    float* out = (float*)d_out;

    pool_kernel<<<16384, 128>>>(x0, x1);          // 65536 warps: B*CT*(T/32)
    gemm_proj_kernel<<<dim3(64, 4), 256>>>(proj_w);
    norm_kernel<<<512, 128>>>();
    band_kernel<<<128, 256>>>();
    fc_kernel<<<128, 256>>>(fc_w, fc_b, out);
}

// round 4
// speedup vs baseline: 1.0628x; 1.0628x over previous
#include <cuda_runtime.h>

// Problem constants
#define BB 2
#define C0 512
#define CT 1024        // total channels
#define TT 1024        // time
#define HW 49          // 7*7
#define DD 128         // SIM_DIM / OUT_DIM
#define LL 101         // LOOKUP
#define W2 50

#define KSPLIT 8

// Scratch (device globals: allowed; no runtime allocation)
__device__ float g_feats[BB * CT * TT];               // [b][c][t]  8 MB
__device__ float g_xpart[KSPLIT][BB * TT * DD];       // k-split partials, 8 MB
__device__ float g_xnorm[BB * TT * DD];               // normalized rows, 1 MB
__device__ float g_band[BB * TT * LL];                // banded sims, 827 KB

// ---- packed fp32x2 helpers (Blackwell) ------------------------------------
__device__ __forceinline__ void fma2(unsigned long long& acc,
                                     unsigned long long a, unsigned long long b) {
    asm("fma.rn.f32x2 %0, %1, %2, %0;" : "+l"(acc) : "l"(a), "l"(b));
}
__device__ __forceinline__ unsigned long long pack2(float x, float y) {
    unsigned long long r;
    asm("mov.b64 %0, {%1, %2};" : "=l"(r) : "f"(x), "f"(y));
    return r;
}
__device__ __forceinline__ float2 unpack2(unsigned long long v) {
    float2 f;
    asm("mov.b64 {%0, %1}, %2;" : "=f"(f.x), "=f"(f.y) : "l"(v));
    return f;
}

// ---------------------------------------------------------------------------
// K1: spatial mean pool.  warp handles (b, c, 32 consecutive t).
// Region = 32*49 = 1568 floats contiguous -> 392 float4, fully coalesced.
// Transpose via smem (stride 49 is odd -> conflict-free reads).
// ---------------------------------------------------------------------------
__global__ void __launch_bounds__(128) pool_kernel(const float* __restrict__ x0,
                                                   const float* __restrict__ x1) {
    __shared__ float sm[4][1568];
    const int w = threadIdx.x >> 5;
    const int lane = threadIdx.x & 31;
    const unsigned wid = blockIdx.x * 4u + w;
    const int tchunk = wid & 31;          // which 32-t chunk
    const int c = (wid >> 5) & 1023;      // channel 0..1023
    const int b = wid >> 15;              // batch

    const float* src = (c < C0)
        ? x0 + ((size_t)((b * C0 + c) * TT) + tchunk * 32) * HW
        : x1 + ((size_t)((b * C0 + (c - C0)) * TT) + tchunk * 32) * HW;

    const float4* s4 = (const float4*)src;
    float4* d4 = (float4*)sm[w];
#pragma unroll
    for (int i = 0; i < 12; i++) d4[i * 32 + lane] = s4[i * 32 + lane];
    if (lane < 8) d4[384 + lane] = s4[384 + lane];
    __syncwarp();

    const float* row = &sm[w][lane * 49];
    float s = 0.f;
#pragma unroll
    for (int j = 0; j < 49; j++) s += row[j];
    g_feats[((b << 10) + c) * TT + tchunk * 32 + lane] = s * (1.0f / 49.0f);
}

// ---------------------------------------------------------------------------
// K2: projection GEMM with packed f32x2 FMA.
// x[b,t,d] = sum_c feats[b,c,t] * proj_w[c,d]
// Tile M=64 (t) x N=128 (d), 128 threads, 8x8 outputs/thread (as 8x4 f32x2).
// K split 8 x 128 across blockIdx.y -> 256 blocks. Partials -> g_xpart.
// ---------------------------------------------------------------------------
__global__ void __launch_bounds__(128) gemm_proj_kernel(const float* __restrict__ proj_w) {
    __shared__ float4 As4[16 * 16];        // [kk][m4]  16 K x 64 M
    __shared__ float4 Bs4[16 * 32];        // [kk][d4]  16 K x 128 N
    const int tid = threadIdx.x;
    const int gm0 = blockIdx.x * 64;       // global row base (b*T + t)
    const int b = gm0 >> 10;
    const int t04 = (gm0 & 1023) >> 2;     // t offset in float4 units
    const int k0base = blockIdx.y * 128;
    const int tm = tid >> 4;               // 0..7  -> rows tm*8..tm*8+7
    const int tn = tid & 15;               // 0..15 -> cols tn*8..tn*8+7

    unsigned long long acc2[8][4];
#pragma unroll
    for (int i = 0; i < 8; i++)
#pragma unroll
        for (int j = 0; j < 4; j++) acc2[i][j] = 0ull;

    const float4* p4 = (const float4*)proj_w;
    const float4* f4 = (const float4*)g_feats;

    for (int kt = 0; kt < 128; kt += 16) {
        const int k0 = k0base + kt;
        // stage A: 16 rows (K) x 16 float4 (64 t), coalesced along t
#pragma unroll
        for (int r = 0; r < 2; r++) {
            int idx = tid + r * 128;
            int kk = idx >> 4, m4 = idx & 15;
            As4[idx] = f4[((b << 10) + k0 + kk) * 256 + t04 + m4];
        }
        // stage B: 16 rows (K) x 32 float4 (128 d)
#pragma unroll
        for (int r = 0; r < 4; r++) {
            int idx = tid + r * 128;
            int kk = idx >> 5, d4i = idx & 31;
            Bs4[idx] = p4[(k0 + kk) * 32 + d4i];
        }
        __syncthreads();
#pragma unroll
        for (int kk = 0; kk < 16; kk++) {
            float4 a0 = As4[kk * 16 + tm * 2];
            float4 a1 = As4[kk * 16 + tm * 2 + 1];
            const ulonglong2* brow = (const ulonglong2*)&Bs4[kk * 32];
            ulonglong2 b0 = brow[tn * 2];
            ulonglong2 b1 = brow[tn * 2 + 1];
            unsigned long long bp[4] = {b0.x, b0.y, b1.x, b1.y};
            float av[8] = {a0.x, a0.y, a0.z, a0.w, a1.x, a1.y, a1.z, a1.w};
#pragma unroll
            for (int i = 0; i < 8; i++) {
                unsigned long long ap = pack2(av[i], av[i]);
#pragma unroll
                for (int j = 0; j < 4; j++) fma2(acc2[i][j], ap, bp[j]);
            }
        }
        __syncthreads();
    }
    float* dst = g_xpart[blockIdx.y];
#pragma unroll
    for (int i = 0; i < 8; i++) {
        ulonglong2 v0, v1;
        v0.x = acc2[i][0]; v0.y = acc2[i][1];
        v1.x = acc2[i][2]; v1.y = acc2[i][3];
        ulonglong2* o = (ulonglong2*)&dst[(gm0 + tm * 8 + i) * DD + tn * 8];
        o[0] = v0; o[1] = v1;
    }
}

// ---------------------------------------------------------------------------
// K3: sum the KSPLIT partials, L2-normalize each 128-dim row.
// One warp per row (lane owns a float4 = 4 dims).
// ---------------------------------------------------------------------------
__global__ void __launch_bounds__(128) norm_kernel() {
    const int row = blockIdx.x * 4 + (threadIdx.x >> 5);   // 0..2047
    const int lane = threadIdx.x & 31;
    float4 v = make_float4(0.f, 0.f, 0.f, 0.f);
#pragma unroll
    for (int s = 0; s < KSPLIT; s++) {
        float4 p = ((const float4*)g_xpart[s])[row * 32 + lane];
        v.x += p.x; v.y += p.y; v.z += p.z; v.w += p.w;
    }
    float sq = v.x * v.x + v.y * v.y + v.z * v.z + v.w * v.w;
#pragma unroll
    for (int o = 16; o; o >>= 1) sq += __shfl_xor_sync(0xFFFFFFFFu, sq, o);
    const float inv = 1.0f / fmaxf(sqrtf(sq), 1e-12f);
    ((float4*)g_xnorm)[row * 32 + lane] =
        make_float4(v.x * inv, v.y * inv, v.z * inv, v.w * inv);
}

// ---------------------------------------------------------------------------
// K4: banded cosine similarity with f32x2 FMA.
// grid (128, 2): blockIdx.x -> 16 t's, blockIdx.y -> j-half (0:[0,51) 1:[51,101)).
// Stage 80 xnorm rows once (full 128 dims), padded -> conflict-free LDS.128.
// ---------------------------------------------------------------------------
__global__ void __launch_bounds__(256) band_kernel() {
    __shared__ ulonglong2 xs[80 * 33];    // 80 rows x (32 float4 + pad)
    const int tid = threadIdx.x;
    const int gt0 = blockIdx.x * 16;
    const int b = gt0 >> 10;
    const int t0 = gt0 & 1023;
    const int by = blockIdx.y;
    const int j0 = by * 51;               // 0 or 51
    const int nj = by ? 50 : 51;
    const int s0 = by ? t0 : t0 - 50;     // staged row base (global s)

    // stage: 80 rows x 32 float4, zero-filled outside [0,T)
    const ulonglong2* xn2 = (const ulonglong2*)g_xnorm;
#pragma unroll
    for (int i = 0; i < 10; i++) {
        int idx = tid + i * 256;
        int r = idx >> 5, q = idx & 31;
        int s = s0 + r;
        ulonglong2 v; v.x = 0ull; v.y = 0ull;
        if (s >= 0 && s < TT) v = xn2[((b << 10) + s) * 32 + q];
        xs[r * 33 + q] = v;
    }
    __syncthreads();

    const int tl = tid >> 4;              // t_local 0..15
    const int tj = tid & 15;              // j residue
    const int ra = by ? tl : tl + 50;     // staged index of row t0+tl
    const int rjb = tl + tj + (by ? 1 : 0);

    unsigned long long acc0[4] = {0ull, 0ull, 0ull, 0ull};
    unsigned long long acc1[4] = {0ull, 0ull, 0ull, 0ull};
#pragma unroll 8
    for (int q = 0; q < 32; q++) {
        ulonglong2 a = xs[ra * 33 + q];
#pragma unroll
        for (int jj = 0; jj < 4; jj++) {
            ulonglong2 bv = xs[(rjb + jj * 16) * 33 + q];
            fma2(acc0[jj], a.x, bv.x);
            fma2(acc1[jj], a.y, bv.y);
        }
    }
#pragma unroll
    for (int jj = 0; jj < 4; jj++) {
        int jl = tj + jj * 16;
        if (jl < nj) {
            float2 p0 = unpack2(acc0[jj]);
            float2 p1 = unpack2(acc1[jj]);
            g_band[(gt0 + tl) * LL + j0 + jl] = (p0.x + p0.y) + (p1.x + p1.y);
        }
    }
}

// ---------------------------------------------------------------------------
// K5: out = relu(band @ fc_w + fc_b).
// grid (128, 2): blockIdx.x -> 16 t rows, blockIdx.y -> 64-d half.
// ---------------------------------------------------------------------------
__global__ void __launch_bounds__(256) fc_kernel(const float* __restrict__ fc_w,
                                                 const float* __restrict__ fc_b,
                                                 float* __restrict__ out) {
    __shared__ float As[16 * LL];         // 1616 floats
    __shared__ float4 Bs[LL * 17];        // 101 rows x (16 float4 + pad)
    const int tid = threadIdx.x;
    const int gt0 = blockIdx.x * 16;
    const int h = blockIdx.y;             // 0/1 -> d-half

#pragma unroll
    for (int i = 0; i < 7; i++) {
        int idx = tid + i * 256;
        if (idx < 16 * LL) As[idx] = g_band[gt0 * LL + idx];
    }
#pragma unroll
    for (int i = 0; i < 7; i++) {
        int idx = tid + i * 256;
        if (idx < LL * 16) {
            int k = idx >> 4, q = idx & 15;
            Bs[k * 17 + q] = ((const float4*)fc_w)[k * 32 + h * 16 + q];
        }
    }
    __syncthreads();

    const int tl = tid >> 4;              // t_local
    const int dg = tid & 15;              // d float4 group within half

    unsigned long long acc0 = 0ull, acc1 = 0ull;
    const float* arow = &As[tl * LL];
#pragma unroll 4
    for (int k = 0; k < LL; k++) {
        unsigned long long ap = pack2(arow[k], arow[k]);
        ulonglong2 b2 = *(const ulonglong2*)&Bs[k * 17 + dg];
        fma2(acc0, ap, b2.x);
        fma2(acc1, ap, b2.y);
    }
    float2 r0 = unpack2(acc0);
    float2 r1 = unpack2(acc1);
    float4 bias = ((const float4*)fc_b)[h * 16 + dg];
    float4 o;
    o.x = fmaxf(r0.x + bias.x, 0.f);
    o.y = fmaxf(r0.y + bias.y, 0.f);
    o.z = fmaxf(r1.x + bias.z, 0.f);
    o.w = fmaxf(r1.y + bias.w, 0.f);
    ((float4*)out)[(gt0 + tl) * 32 + h * 16 + dg] = o;
}

// ---------------------------------------------------------------------------
extern "C" void kernel_launch(void* const* d_in, const int* in_sizes, int n_in,
                              void* d_out, int out_size) {
    const float* x0     = (const float*)d_in[0];
    const float* x1     = (const float*)d_in[1];
    const float* proj_w = (const float*)d_in[2];
    const float* fc_w   = (const float*)d_in[3];
    const float* fc_b   = (const float*)d_in[4];
    float* out = (float*)d_out;

    pool_kernel<<<16384, 128>>>(x0, x1);
    gemm_proj_kernel<<<dim3(32, KSPLIT), 128>>>(proj_w);
    norm_kernel<<<512, 128>>>();
    band_kernel<<<dim3(128, 2), 256>>>();
    fc_kernel<<<dim3(128, 2), 256>>>(fc_w, fc_b, out);
}

// round 5
// speedup vs baseline: 1.1001x; 1.0351x over previous
#include <cuda_runtime.h>
#include <cstdint>

// Problem constants
#define BB 2
#define C0 512
#define CT 1024        // total channels
#define TT 1024        // time
#define HW 49          // 7*7
#define DD 128         // SIM_DIM / OUT_DIM
#define LL 101         // LOOKUP
#define W2 50

#define KSPLIT 4

// Scratch (device globals: allowed; no runtime allocation)
__device__ float g_feats[BB * CT * TT];               // [b][c][t]  8 MB
__device__ float g_xpart[KSPLIT][BB * TT * DD];       // k-split partials
__device__ float g_xnorm[BB * TT * DD];               // normalized rows, 1 MB
__device__ float g_band[BB * TT * LL];                // banded sims, 827 KB

// ---- packed fp32x2 helpers (Blackwell) ------------------------------------
__device__ __forceinline__ void fma2(unsigned long long& acc,
                                     unsigned long long a, unsigned long long b) {
    asm("fma.rn.f32x2 %0, %1, %2, %0;" : "+l"(acc) : "l"(a), "l"(b));
}
__device__ __forceinline__ unsigned long long pack2(float x, float y) {
    unsigned long long r;
    asm("mov.b64 %0, {%1, %2};" : "=l"(r) : "f"(x), "f"(y));
    return r;
}
__device__ __forceinline__ float2 unpack2(unsigned long long v) {
    float2 f;
    asm("mov.b64 {%0, %1}, %2;" : "=f"(f.x), "=f"(f.y) : "l"(v));
    return f;
}
__device__ __forceinline__ uint32_t f2tf32(float x) {
    uint32_t r;
    asm("cvt.rna.tf32.f32 %0, %1;" : "=r"(r) : "f"(x));
    return r;
}
__device__ __forceinline__ void mma_tf32(float c[4], uint32_t a0, uint32_t a1,
                                         uint32_t a2, uint32_t a3,
                                         uint32_t b0, uint32_t b1) {
    asm("mma.sync.aligned.m16n8k8.row.col.f32.tf32.tf32.f32 "
        "{%0,%1,%2,%3}, {%4,%5,%6,%7}, {%8,%9}, {%0,%1,%2,%3};"
        : "+f"(c[0]), "+f"(c[1]), "+f"(c[2]), "+f"(c[3])
        : "r"(a0), "r"(a1), "r"(a2), "r"(a3), "r"(b0), "r"(b1));
}

// ---------------------------------------------------------------------------
// K1: spatial mean pool.  warp handles (b, c, 32 consecutive t).
// ---------------------------------------------------------------------------
__global__ void __launch_bounds__(128) pool_kernel(const float* __restrict__ x0,
                                                   const float* __restrict__ x1) {
    __shared__ float sm[4][1568];
    const int w = threadIdx.x >> 5;
    const int lane = threadIdx.x & 31;
    const unsigned wid = blockIdx.x * 4u + w;
    const int tchunk = wid & 31;
    const int c = (wid >> 5) & 1023;
    const int b = wid >> 15;

    const float* src = (c < C0)
        ? x0 + ((size_t)((b * C0 + c) * TT) + tchunk * 32) * HW
        : x1 + ((size_t)((b * C0 + (c - C0)) * TT) + tchunk * 32) * HW;

    const float4* s4 = (const float4*)src;
    float4* d4 = (float4*)sm[w];
#pragma unroll
    for (int i = 0; i < 12; i++) d4[i * 32 + lane] = s4[i * 32 + lane];
    if (lane < 8) d4[384 + lane] = s4[384 + lane];
    __syncwarp();

    const float* row = &sm[w][lane * 49];
    float s = 0.f;
#pragma unroll
    for (int j = 0; j < 49; j++) s += row[j];
    g_feats[((b << 10) + c) * TT + tchunk * 32 + lane] = s * (1.0f / 49.0f);
}

// ---------------------------------------------------------------------------
// K2: projection GEMM with TF32 mma.sync (m16n8k8).
// x[b,t,d] = sum_c feats[b,c,t] * proj_w[c,d]
// Block: M=32 (t) x N=128 (d) x K=256, 256 threads (8 warps, warp grid 2x4).
// KSPLIT=4 over K -> grid (64, 4) = 256 blocks. Partials -> g_xpart.
// Smem pads: A stride 40, B stride 136 -> conflict-free fragment LDS.
// ---------------------------------------------------------------------------
__global__ void __launch_bounds__(256) gemm_proj_kernel(const float* __restrict__ proj_w) {
    __shared__ uint32_t As[32 * 40];       // [k][m] tf32
    __shared__ uint32_t Bs[32 * 136];      // [k][n] tf32
    const int tid = threadIdx.x;
    const int gm0 = blockIdx.x * 32;       // global row base (b*T + t)
    const int b = gm0 >> 10;
    const int t04 = (gm0 & 1023) >> 2;
    const int k0base = blockIdx.y * 256;

    const int w = tid >> 5;
    const int lane = tid & 31;
    const int m0 = (w & 1) * 16;
    const int n0 = (w >> 1) * 32;
    const int gid = lane >> 2;             // 0..7
    const int tig = lane & 3;              // 0..3

    float c[4][4];
#pragma unroll
    for (int i = 0; i < 4; i++)
#pragma unroll
        for (int j = 0; j < 4; j++) c[i][j] = 0.f;

    const float4* p4 = (const float4*)proj_w;
    const float4* f4 = (const float4*)g_feats;

    for (int kt = 0; kt < 256; kt += 32) {
        const int k0 = k0base + kt;
        // stage A: 32 k-rows x 32 t, one float4 per thread
        {
            int kk = tid >> 3, m4 = tid & 7;
            float4 v = f4[((b << 10) + k0 + kk) * 256 + t04 + m4];
            uint32_t* dst = &As[kk * 40 + m4 * 4];
            dst[0] = f2tf32(v.x); dst[1] = f2tf32(v.y);
            dst[2] = f2tf32(v.z); dst[3] = f2tf32(v.w);
        }
        // stage B: 32 k-rows x 128 d, four float4 per thread
#pragma unroll
        for (int r = 0; r < 4; r++) {
            int idx = tid + r * 256;
            int kk = idx >> 5, n4 = idx & 31;
            float4 v = p4[(k0 + kk) * 32 + n4];
            uint32_t* dst = &Bs[kk * 136 + n4 * 4];
            dst[0] = f2tf32(v.x); dst[1] = f2tf32(v.y);
            dst[2] = f2tf32(v.z); dst[3] = f2tf32(v.w);
        }
        __syncthreads();
#pragma unroll
        for (int k8 = 0; k8 < 32; k8 += 8) {
            uint32_t a0 = As[(k8 + tig) * 40 + m0 + gid];
            uint32_t a1 = As[(k8 + tig) * 40 + m0 + gid + 8];
            uint32_t a2 = As[(k8 + tig + 4) * 40 + m0 + gid];
            uint32_t a3 = As[(k8 + tig + 4) * 40 + m0 + gid + 8];
#pragma unroll
            for (int nf = 0; nf < 4; nf++) {
                int n = n0 + nf * 8 + gid;
                uint32_t b0 = Bs[(k8 + tig) * 136 + n];
                uint32_t b1 = Bs[(k8 + tig + 4) * 136 + n];
                mma_tf32(c[nf], a0, a1, a2, a3, b0, b1);
            }
        }
        __syncthreads();
    }
    float* dst = g_xpart[blockIdx.y];
#pragma unroll
    for (int nf = 0; nf < 4; nf++) {
        int col = n0 + nf * 8 + tig * 2;
        *(float2*)&dst[(gm0 + m0 + gid) * DD + col]     = make_float2(c[nf][0], c[nf][1]);
        *(float2*)&dst[(gm0 + m0 + gid + 8) * DD + col] = make_float2(c[nf][2], c[nf][3]);
    }
}

// ---------------------------------------------------------------------------
// K3: sum KSPLIT partials, L2-normalize each 128-dim row. Warp per row.
// ---------------------------------------------------------------------------
__global__ void __launch_bounds__(128) norm_kernel() {
    const int row = blockIdx.x * 4 + (threadIdx.x >> 5);   // 0..2047
    const int lane = threadIdx.x & 31;
    float4 v = make_float4(0.f, 0.f, 0.f, 0.f);
#pragma unroll
    for (int s = 0; s < KSPLIT; s++) {
        float4 p = ((const float4*)g_xpart[s])[row * 32 + lane];
        v.x += p.x; v.y += p.y; v.z += p.z; v.w += p.w;
    }
    float sq = v.x * v.x + v.y * v.y + v.z * v.z + v.w * v.w;
#pragma unroll
    for (int o = 16; o; o >>= 1) sq += __shfl_xor_sync(0xFFFFFFFFu, sq, o);
    const float inv = 1.0f / fmaxf(sqrtf(sq), 1e-12f);
    ((float4*)g_xnorm)[row * 32 + lane] =
        make_float4(v.x * inv, v.y * inv, v.z * inv, v.w * inv);
}

// ---------------------------------------------------------------------------
// K4: banded cosine similarity, diagonal-parameterized (b-rows shared across t).
// grid (128, 2): bx -> 16 t's, by -> j-half (0: j in [0,50], 1: j in [51,100]).
// Stage 66 consecutive xnorm rows; thread = 2 t's x 5 s-rows -> 7 LDS.128 per
// 20 fma2.  Output j = s_idx - tl (+50 for half 1), masked to the half.
// ---------------------------------------------------------------------------
__global__ void __launch_bounds__(128) band_kernel() {
    __shared__ ulonglong2 xs[66 * 33];    // 66 rows x (32 float4 + pad)
    const int tid = threadIdx.x;
    const int gt0 = blockIdx.x * 16;
    const int b = gt0 >> 10;
    const int t0 = gt0 & 1023;
    const int by = blockIdx.y;
    const int s0 = by ? t0 : t0 - W2;     // staged global row base

    // stage 66 rows x 32 float4, zero-filled outside [0,T)
    const ulonglong2* xn2 = (const ulonglong2*)g_xnorm;
#pragma unroll
    for (int i = 0; i < 17; i++) {
        int idx = tid + i * 128;
        if (idx < 66 * 32) {
            int r = idx >> 5, q = idx & 31;
            int s = s0 + r;
            ulonglong2 v; v.x = 0ull; v.y = 0ull;
            if (s >= 0 && s < TT) v = xn2[((b << 10) + s) * 32 + q];
            xs[r * 33 + q] = v;
        }
    }
    __syncthreads();

    const int tg = tid >> 4;              // 0..7 -> t_local {2tg, 2tg+1}
    const int sg = tid & 15;              // s_idx = sg + ss*16, ss in 0..4
    const int tl0 = tg * 2;
    const int ra0 = (by ? 0 : W2) + tl0;  // staged idx of a-row for tl0

    unsigned long long acc[2][5];
#pragma unroll
    for (int i = 0; i < 2; i++)
#pragma unroll
        for (int s = 0; s < 5; s++) acc[i][s] = 0ull;

    int srow[5];
#pragma unroll
    for (int ss = 0; ss < 5; ss++) {
        int si = sg + ss * 16;
        srow[ss] = (si < 66 ? si : 65);   // clamp; masked at write
    }

#pragma unroll 8
    for (int q = 0; q < 32; q++) {
        ulonglong2 a0 = xs[ra0 * 33 + q];
        ulonglong2 a1 = xs[(ra0 + 1) * 33 + q];
#pragma unroll
        for (int ss = 0; ss < 5; ss++) {
            ulonglong2 bv = xs[srow[ss] * 33 + q];
            fma2(acc[0][ss], a0.x, bv.x);
            fma2(acc[0][ss], a0.y, bv.y);
            fma2(acc[1][ss], a1.x, bv.x);
            fma2(acc[1][ss], a1.y, bv.y);
        }
    }

#pragma unroll
    for (int i = 0; i < 2; i++) {
        int tl = tl0 + i;
#pragma unroll
        for (int ss = 0; ss < 5; ss++) {
            int si = sg + ss * 16;
            int d = si - tl;              // j (half 0) or j-50 (half 1)
            bool ok = by ? (d >= 1 && d <= 50) : (d >= 0 && d <= 50);
            if (ok && si < 66) {
                int j = by ? d + W2 : d;
                float2 p = unpack2(acc[i][ss]);
                g_band[(gt0 + tl) * LL + j] = p.x + p.y;
            }
        }
    }
}

// ---------------------------------------------------------------------------
// K5: out = relu(band @ fc_w + fc_b).
// grid (128, 2): bx -> 16 t rows, by -> 64-d half.
// ---------------------------------------------------------------------------
__global__ void __launch_bounds__(256) fc_kernel(const float* __restrict__ fc_w,
                                                 const float* __restrict__ fc_b,
                                                 float* __restrict__ out) {
    __shared__ float As[16 * LL];
    __shared__ float4 Bs[LL * 17];
    const int tid = threadIdx.x;
    const int gt0 = blockIdx.x * 16;
    const int h = blockIdx.y;

#pragma unroll
    for (int i = 0; i < 7; i++) {
        int idx = tid + i * 256;
        if (idx < 16 * LL) As[idx] = g_band[gt0 * LL + idx];
    }
#pragma unroll
    for (int i = 0; i < 7; i++) {
        int idx = tid + i * 256;
        if (idx < LL * 16) {
            int k = idx >> 4, q = idx & 15;
            Bs[k * 17 + q] = ((const float4*)fc_w)[k * 32 + h * 16 + q];
        }
    }
    __syncthreads();

    const int tl = tid >> 4;
    const int dg = tid & 15;

    unsigned long long acc0 = 0ull, acc1 = 0ull;
    const float* arow = &As[tl * LL];
#pragma unroll 4
    for (int k = 0; k < LL; k++) {
        unsigned long long ap = pack2(arow[k], arow[k]);
        ulonglong2 b2 = *(const ulonglong2*)&Bs[k * 17 + dg];
        fma2(acc0, ap, b2.x);
        fma2(acc1, ap, b2.y);
    }
    float2 r0 = unpack2(acc0);
    float2 r1 = unpack2(acc1);
    float4 bias = ((const float4*)fc_b)[h * 16 + dg];
    float4 o;
    o.x = fmaxf(r0.x + bias.x, 0.f);
    o.y = fmaxf(r0.y + bias.y, 0.f);
    o.z = fmaxf(r1.x + bias.z, 0.f);
    o.w = fmaxf(r1.y + bias.w, 0.f);
    ((float4*)out)[(gt0 + tl) * 32 + h * 16 + dg] = o;
}

// ---------------------------------------------------------------------------
extern "C" void kernel_launch(void* const* d_in, const int* in_sizes, int n_in,
                              void* d_out, int out_size) {
    const float* x0     = (const float*)d_in[0];
    const float* x1     = (const float*)d_in[1];
    const float* proj_w = (const float*)d_in[2];
    const float* fc_w   = (const float*)d_in[3];
    const float* fc_b   = (const float*)d_in[4];
    float* out = (float*)d_out;

    pool_kernel<<<16384, 128>>>(x0, x1);
    gemm_proj_kernel<<<dim3(64, KSPLIT), 256>>>(proj_w);
    norm_kernel<<<512, 128>>>();
    band_kernel<<<dim3(128, 2), 128>>>();
    fc_kernel<<<dim3(128, 2), 256>>>(fc_w, fc_b, out);
}

// round 6
// speedup vs baseline: 1.2295x; 1.1176x over previous
#include <cuda_runtime.h>
#include <cstdint>

// Problem constants
#define BB 2
#define C0 512
#define CT 1024        // total channels
#define TT 1024        // time
#define HW 49          // 7*7
#define DD 128         // SIM_DIM / OUT_DIM
#define LL 101         // LOOKUP
#define W2 50

#define KSPLIT 4

// Scratch (device globals: allowed; no runtime allocation)
__device__ float g_feats[BB * CT * TT];               // [b][c][t]  8 MB
__device__ float g_xpart[KSPLIT][BB * TT * DD];       // k-split partials
__device__ float g_xnorm[BB * TT * DD];               // normalized rows, 1 MB
__device__ float g_band[BB * TT * LL];                // banded sims, 827 KB

// ---- packed fp32x2 helpers (Blackwell) ------------------------------------
__device__ __forceinline__ void fma2(unsigned long long& acc,
                                     unsigned long long a, unsigned long long b) {
    asm("fma.rn.f32x2 %0, %1, %2, %0;" : "+l"(acc) : "l"(a), "l"(b));
}
__device__ __forceinline__ unsigned long long pack2(float x, float y) {
    unsigned long long r;
    asm("mov.b64 %0, {%1, %2};" : "=l"(r) : "f"(x), "f"(y));
    return r;
}
__device__ __forceinline__ float2 unpack2(unsigned long long v) {
    float2 f;
    asm("mov.b64 {%0, %1}, %2;" : "=f"(f.x), "=f"(f.y) : "l"(v));
    return f;
}
__device__ __forceinline__ uint32_t f2tf32(float x) {
    uint32_t r;
    asm("cvt.rna.tf32.f32 %0, %1;" : "=r"(r) : "f"(x));
    return r;
}
__device__ __forceinline__ void mma_tf32(float c[4], uint32_t a0, uint32_t a1,
                                         uint32_t a2, uint32_t a3,
                                         uint32_t b0, uint32_t b1) {
    asm("mma.sync.aligned.m16n8k8.row.col.f32.tf32.tf32.f32 "
        "{%0,%1,%2,%3}, {%4,%5,%6,%7}, {%8,%9}, {%0,%1,%2,%3};"
        : "+f"(c[0]), "+f"(c[1]), "+f"(c[2]), "+f"(c[3])
        : "r"(a0), "r"(a1), "r"(a2), "r"(a3), "r"(b0), "r"(b1));
}

// ---- cp.async helpers ------------------------------------------------------
__device__ __forceinline__ void cpasync16(uint32_t s, const void* g) {
    asm volatile("cp.async.cg.shared.global [%0], [%1], 16;" :: "r"(s), "l"(g));
}
__device__ __forceinline__ void cp_commit() {
    asm volatile("cp.async.commit_group;");
}
template <int N> __device__ __forceinline__ void cp_wait() {
    asm volatile("cp.async.wait_group %0;" :: "n"(N));
}

// ---------------------------------------------------------------------------
// K1: spatial mean pool — persistent channel-streaming warps + cp.async
// double buffering.  Warp = one (b,c) channel (196 KB sequential stream),
// 32 chunks of (32 t x 49).  cp.async.cg keeps loads off the L1tex front-batch
// path and overlaps chunk k+1's HBM traffic with chunk k's reduction.
// Grid 1024 x 64 thr (2 warps/block, 25 KB smem) -> ~18 warps/SM, 1 wave.
// ---------------------------------------------------------------------------
__global__ void __launch_bounds__(64) pool_kernel(const float* __restrict__ x0,
                                                  const float* __restrict__ x1) {
    __shared__ float sm[2][2][1568];       // [warp][buf][chunk]
    const int w = threadIdx.x >> 5;
    const int lane = threadIdx.x & 31;
    const int ch = blockIdx.x * 2 + w;     // 0..2047
    const int b = ch >> 10;
    const int c = ch & 1023;

    const float* src = (c < C0)
        ? x0 + (size_t)(b * C0 + c) * TT * HW
        : x1 + (size_t)(b * C0 + (c - C0)) * TT * HW;

    uint32_t sb[2];
    sb[0] = (uint32_t)__cvta_generic_to_shared(&sm[w][0][0]);
    sb[1] = (uint32_t)__cvta_generic_to_shared(&sm[w][1][0]);

    // issue chunk k into buffer buf (392 float4 per chunk, per warp)
    auto issue = [&](int k, int buf) {
        const float4* g = (const float4*)(src + (size_t)k * 1568);
        uint32_t s = sb[buf];
#pragma unroll
        for (int i = 0; i < 12; i++)
            cpasync16(s + (i * 32 + lane) * 16, g + i * 32 + lane);
        if (lane < 8)
            cpasync16(s + (384 + lane) * 16, g + 384 + lane);
        cp_commit();
    };

    issue(0, 0);
    issue(1, 1);

    float* dst = &g_feats[(size_t)ch * TT];

    for (int k = 0; k < 32; k++) {
        if (k < 31) cp_wait<1>(); else cp_wait<0>();
        __syncwarp();
        const float* row = &sm[w][k & 1][lane * 49];
        float s = 0.f;
#pragma unroll
        for (int j = 0; j < 49; j++) s += row[j];
        dst[k * 32 + lane] = s * (1.0f / 49.0f);
        __syncwarp();
        if (k + 2 < 32) issue(k + 2, k & 1);
    }
}

// ---------------------------------------------------------------------------
// K2: projection GEMM with TF32 mma.sync (m16n8k8).  (unchanged from R5)
// ---------------------------------------------------------------------------
__global__ void __launch_bounds__(256) gemm_proj_kernel(const float* __restrict__ proj_w) {
    __shared__ uint32_t As[32 * 40];       // [k][m] tf32
    __shared__ uint32_t Bs[32 * 136];      // [k][n] tf32
    const int tid = threadIdx.x;
    const int gm0 = blockIdx.x * 32;       // global row base (b*T + t)
    const int b = gm0 >> 10;
    const int t04 = (gm0 & 1023) >> 2;
    const int k0base = blockIdx.y * 256;

    const int w = tid >> 5;
    const int lane = tid & 31;
    const int m0 = (w & 1) * 16;
    const int n0 = (w >> 1) * 32;
    const int gid = lane >> 2;             // 0..7
    const int tig = lane & 3;              // 0..3

    float c[4][4];
#pragma unroll
    for (int i = 0; i < 4; i++)
#pragma unroll
        for (int j = 0; j < 4; j++) c[i][j] = 0.f;

    const float4* p4 = (const float4*)proj_w;
    const float4* f4 = (const float4*)g_feats;

    for (int kt = 0; kt < 256; kt += 32) {
        const int k0 = k0base + kt;
        {
            int kk = tid >> 3, m4 = tid & 7;
            float4 v = f4[((b << 10) + k0 + kk) * 256 + t04 + m4];
            uint32_t* dst = &As[kk * 40 + m4 * 4];
            dst[0] = f2tf32(v.x); dst[1] = f2tf32(v.y);
            dst[2] = f2tf32(v.z); dst[3] = f2tf32(v.w);
        }
#pragma unroll
        for (int r = 0; r < 4; r++) {
            int idx = tid + r * 256;
            int kk = idx >> 5, n4 = idx & 31;
            float4 v = p4[(k0 + kk) * 32 + n4];
            uint32_t* dst = &Bs[kk * 136 + n4 * 4];
            dst[0] = f2tf32(v.x); dst[1] = f2tf32(v.y);
            dst[2] = f2tf32(v.z); dst[3] = f2tf32(v.w);
        }
        __syncthreads();
#pragma unroll
        for (int k8 = 0; k8 < 32; k8 += 8) {
            uint32_t a0 = As[(k8 + tig) * 40 + m0 + gid];
            uint32_t a1 = As[(k8 + tig) * 40 + m0 + gid + 8];
            uint32_t a2 = As[(k8 + tig + 4) * 40 + m0 + gid];
            uint32_t a3 = As[(k8 + tig + 4) * 40 + m0 + gid + 8];
#pragma unroll
            for (int nf = 0; nf < 4; nf++) {
                int n = n0 + nf * 8 + gid;
                uint32_t b0 = Bs[(k8 + tig) * 136 + n];
                uint32_t b1 = Bs[(k8 + tig + 4) * 136 + n];
                mma_tf32(c[nf], a0, a1, a2, a3, b0, b1);
            }
        }
        __syncthreads();
    }
    float* dst = g_xpart[blockIdx.y];
#pragma unroll
    for (int nf = 0; nf < 4; nf++) {
        int col = n0 + nf * 8 + tig * 2;
        *(float2*)&dst[(gm0 + m0 + gid) * DD + col]     = make_float2(c[nf][0], c[nf][1]);
        *(float2*)&dst[(gm0 + m0 + gid + 8) * DD + col] = make_float2(c[nf][2], c[nf][3]);
    }
}

// ---------------------------------------------------------------------------
// K3: sum KSPLIT partials, L2-normalize each 128-dim row. Warp per row.
// ---------------------------------------------------------------------------
__global__ void __launch_bounds__(128) norm_kernel() {
    const int row = blockIdx.x * 4 + (threadIdx.x >> 5);   // 0..2047
    const int lane = threadIdx.x & 31;
    float4 v = make_float4(0.f, 0.f, 0.f, 0.f);
#pragma unroll
    for (int s = 0; s < KSPLIT; s++) {
        float4 p = ((const float4*)g_xpart[s])[row * 32 + lane];
        v.x += p.x; v.y += p.y; v.z += p.z; v.w += p.w;
    }
    float sq = v.x * v.x + v.y * v.y + v.z * v.z + v.w * v.w;
#pragma unroll
    for (int o = 16; o; o >>= 1) sq += __shfl_xor_sync(0xFFFFFFFFu, sq, o);
    const float inv = 1.0f / fmaxf(sqrtf(sq), 1e-12f);
    ((float4*)g_xnorm)[row * 32 + lane] =
        make_float4(v.x * inv, v.y * inv, v.z * inv, v.w * inv);
}

// ---------------------------------------------------------------------------
// K4: banded cosine similarity, diagonal-parameterized. (unchanged from R5)
// ---------------------------------------------------------------------------
__global__ void __launch_bounds__(128) band_kernel() {
    __shared__ ulonglong2 xs[66 * 33];    // 66 rows x (32 float4 + pad)
    const int tid = threadIdx.x;
    const int gt0 = blockIdx.x * 16;
    const int b = gt0 >> 10;
    const int t0 = gt0 & 1023;
    const int by = blockIdx.y;
    const int s0 = by ? t0 : t0 - W2;     // staged global row base

    const ulonglong2* xn2 = (const ulonglong2*)g_xnorm;
#pragma unroll
    for (int i = 0; i < 17; i++) {
        int idx = tid + i * 128;
        if (idx < 66 * 32) {
            int r = idx >> 5, q = idx & 31;
            int s = s0 + r;
            ulonglong2 v; v.x = 0ull; v.y = 0ull;
            if (s >= 0 && s < TT) v = xn2[((b << 10) + s) * 32 + q];
            xs[r * 33 + q] = v;
        }
    }
    __syncthreads();

    const int tg = tid >> 4;              // 0..7 -> t_local {2tg, 2tg+1}
    const int sg = tid & 15;              // s_idx = sg + ss*16, ss in 0..4
    const int tl0 = tg * 2;
    const int ra0 = (by ? 0 : W2) + tl0;  // staged idx of a-row for tl0

    unsigned long long acc[2][5];
#pragma unroll
    for (int i = 0; i < 2; i++)
#pragma unroll
        for (int s = 0; s < 5; s++) acc[i][s] = 0ull;

    int srow[5];
#pragma unroll
    for (int ss = 0; ss < 5; ss++) {
        int si = sg + ss * 16;
        srow[ss] = (si < 66 ? si : 65);   // clamp; masked at write
    }

#pragma unroll 8
    for (int q = 0; q < 32; q++) {
        ulonglong2 a0 = xs[ra0 * 33 + q];
        ulonglong2 a1 = xs[(ra0 + 1) * 33 + q];
#pragma unroll
        for (int ss = 0; ss < 5; ss++) {
            ulonglong2 bv = xs[srow[ss] * 33 + q];
            fma2(acc[0][ss], a0.x, bv.x);
            fma2(acc[0][ss], a0.y, bv.y);
            fma2(acc[1][ss], a1.x, bv.x);
            fma2(acc[1][ss], a1.y, bv.y);
        }
    }

#pragma unroll
    for (int i = 0; i < 2; i++) {
        int tl = tl0 + i;
#pragma unroll
        for (int ss = 0; ss < 5; ss++) {
            int si = sg + ss * 16;
            int d = si - tl;              // j (half 0) or j-50 (half 1)
            bool ok = by ? (d >= 1 && d <= 50) : (d >= 0 && d <= 50);
            if (ok && si < 66) {
                int j = by ? d + W2 : d;
                float2 p = unpack2(acc[i][ss]);
                g_band[(gt0 + tl) * LL + j] = p.x + p.y;
            }
        }
    }
}

// ---------------------------------------------------------------------------
// K5: out = relu(band @ fc_w + fc_b).  (unchanged from R5)
// ---------------------------------------------------------------------------
__global__ void __launch_bounds__(256) fc_kernel(const float* __restrict__ fc_w,
                                                 const float* __restrict__ fc_b,
                                                 float* __restrict__ out) {
    __shared__ float As[16 * LL];
    __shared__ float4 Bs[LL * 17];
    const int tid = threadIdx.x;
    const int gt0 = blockIdx.x * 16;
    const int h = blockIdx.y;

#pragma unroll
    for (int i = 0; i < 7; i++) {
        int idx = tid + i * 256;
        if (idx < 16 * LL) As[idx] = g_band[gt0 * LL + idx];
    }
#pragma unroll
    for (int i = 0; i < 7; i++) {
        int idx = tid + i * 256;
        if (idx < LL * 16) {
            int k = idx >> 4, q = idx & 15;
            Bs[k * 17 + q] = ((const float4*)fc_w)[k * 32 + h * 16 + q];
        }
    }
    __syncthreads();

    const int tl = tid >> 4;
    const int dg = tid & 15;

    unsigned long long acc0 = 0ull, acc1 = 0ull;
    const float* arow = &As[tl * LL];
#pragma unroll 4
    for (int k = 0; k < LL; k++) {
        unsigned long long ap = pack2(arow[k], arow[k]);
        ulonglong2 b2 = *(const ulonglong2*)&Bs[k * 17 + dg];
        fma2(acc0, ap, b2.x);
        fma2(acc1, ap, b2.y);
    }
    float2 r0 = unpack2(acc0);
    float2 r1 = unpack2(acc1);
    float4 bias = ((const float4*)fc_b)[h * 16 + dg];
    float4 o;
    o.x = fmaxf(r0.x + bias.x, 0.f);
    o.y = fmaxf(r0.y + bias.y, 0.f);
    o.z = fmaxf(r1.x + bias.z, 0.f);
    o.w = fmaxf(r1.y + bias.w, 0.f);
    ((float4*)out)[(gt0 + tl) * 32 + h * 16 + dg] = o;
}

// ---------------------------------------------------------------------------
extern "C" void kernel_launch(void* const* d_in, const int* in_sizes, int n_in,
                              void* d_out, int out_size) {
    const float* x0     = (const float*)d_in[0];
    const float* x1     = (const float*)d_in[1];
    const float* proj_w = (const float*)d_in[2];
    const float* fc_w   = (const float*)d_in[3];
    const float* fc_b   = (const float*)d_in[4];
    float* out = (float*)d_out;

    pool_kernel<<<1024, 64>>>(x0, x1);
    gemm_proj_kernel<<<dim3(64, KSPLIT), 256>>>(proj_w);
    norm_kernel<<<512, 128>>>();
    band_kernel<<<dim3(128, 2), 128>>>();
    fc_kernel<<<dim3(128, 2), 256>>>(fc_w, fc_b, out);
}

// round 7
// speedup vs baseline: 1.2748x; 1.0368x over previous
#include <cuda_runtime.h>
#include <cstdint>

// Problem constants
#define BB 2
#define C0 512
#define CT 1024        // total channels
#define TT 1024        // time
#define HW 49          // 7*7
#define DD 128         // SIM_DIM / OUT_DIM
#define LL 101         // LOOKUP
#define W2 50

#define KSPLIT 8

// Scratch (device globals: allowed; no runtime allocation)
__device__ float g_feats[BB * CT * TT];               // [b][c][t]  8 MB
__device__ float g_xpart[KSPLIT][BB * TT * DD];       // k-split partials
__device__ float g_xnorm[BB * TT * DD];               // normalized rows, 1 MB
__device__ float g_band[BB * TT * LL];                // banded sims, 827 KB

// ---- packed fp32x2 helpers (Blackwell) ------------------------------------
__device__ __forceinline__ void fma2(unsigned long long& acc,
                                     unsigned long long a, unsigned long long b) {
    asm("fma.rn.f32x2 %0, %1, %2, %0;" : "+l"(acc) : "l"(a), "l"(b));
}
__device__ __forceinline__ unsigned long long pack2(float x, float y) {
    unsigned long long r;
    asm("mov.b64 %0, {%1, %2};" : "=l"(r) : "f"(x), "f"(y));
    return r;
}
__device__ __forceinline__ float2 unpack2(unsigned long long v) {
    float2 f;
    asm("mov.b64 {%0, %1}, %2;" : "=f"(f.x), "=f"(f.y) : "l"(v));
    return f;
}
__device__ __forceinline__ uint32_t f2tf32(float x) {
    uint32_t r;
    asm("cvt.rna.tf32.f32 %0, %1;" : "=r"(r) : "f"(x));
    return r;
}
__device__ __forceinline__ void mma_tf32(float c[4], uint32_t a0, uint32_t a1,
                                         uint32_t a2, uint32_t a3,
                                         uint32_t b0, uint32_t b1) {
    asm("mma.sync.aligned.m16n8k8.row.col.f32.tf32.tf32.f32 "
        "{%0,%1,%2,%3}, {%4,%5,%6,%7}, {%8,%9}, {%0,%1,%2,%3};"
        : "+f"(c[0]), "+f"(c[1]), "+f"(c[2]), "+f"(c[3])
        : "r"(a0), "r"(a1), "r"(a2), "r"(a3), "r"(b0), "r"(b1));
}

// ---- cp.async helpers ------------------------------------------------------
__device__ __forceinline__ void cpasync16(uint32_t s, const void* g) {
    asm volatile("cp.async.cg.shared.global [%0], [%1], 16;" :: "r"(s), "l"(g));
}
__device__ __forceinline__ void cp_commit() {
    asm volatile("cp.async.commit_group;");
}
template <int N> __device__ __forceinline__ void cp_wait() {
    asm volatile("cp.async.wait_group %0;" :: "n"(N));
}

// ---------------------------------------------------------------------------
// K1: spatial mean pool — channel-streaming warps + cp.async double buffering.
// One warp per block (12.5 KB smem) -> 18 resident warps/SM, single wave of
// 2048 blocks.  Warp = one (b,c) channel, 32 chunks of (32 t x 49).
// ---------------------------------------------------------------------------
__global__ void __launch_bounds__(32) pool_kernel(const float* __restrict__ x0,
                                                  const float* __restrict__ x1) {
    __shared__ float sm[2][1568];
    const int lane = threadIdx.x;
    const int ch = blockIdx.x;             // 0..2047
    const int b = ch >> 10;
    const int c = ch & 1023;

    const float* src = (c < C0)
        ? x0 + (size_t)(b * C0 + c) * TT * HW
        : x1 + (size_t)(b * C0 + (c - C0)) * TT * HW;

    uint32_t sb[2];
    sb[0] = (uint32_t)__cvta_generic_to_shared(&sm[0][0]);
    sb[1] = (uint32_t)__cvta_generic_to_shared(&sm[1][0]);

    auto issue = [&](int k, int buf) {
        const float4* g = (const float4*)(src + (size_t)k * 1568);
        uint32_t s = sb[buf];
#pragma unroll
        for (int i = 0; i < 12; i++)
            cpasync16(s + (i * 32 + lane) * 16, g + i * 32 + lane);
        if (lane < 8)
            cpasync16(s + (384 + lane) * 16, g + 384 + lane);
        cp_commit();
    };

    issue(0, 0);
    issue(1, 1);

    float* dst = &g_feats[(size_t)ch * TT];

    for (int k = 0; k < 32; k++) {
        if (k < 31) cp_wait<1>(); else cp_wait<0>();
        __syncwarp();
        const float* row = &sm[k & 1][lane * 49];
        float s = 0.f;
#pragma unroll
        for (int j = 0; j < 49; j++) s += row[j];
        dst[k * 32 + lane] = s * (1.0f / 49.0f);
        __syncwarp();
        if (k + 2 < 32) issue(k + 2, k & 1);
    }
}

// ---------------------------------------------------------------------------
// K2: projection GEMM with TF32 mma.sync (m16n8k8).
// Block: M=32 x N=128 x K=128, 256 threads.  KSPLIT=8 -> grid (64,8)=512.
// ---------------------------------------------------------------------------
__global__ void __launch_bounds__(256) gemm_proj_kernel(const float* __restrict__ proj_w) {
    __shared__ uint32_t As[32 * 40];       // [k][m] tf32
    __shared__ uint32_t Bs[32 * 136];      // [k][n] tf32
    const int tid = threadIdx.x;
    const int gm0 = blockIdx.x * 32;       // global row base (b*T + t)
    const int b = gm0 >> 10;
    const int t04 = (gm0 & 1023) >> 2;
    const int k0base = blockIdx.y * 128;

    const int w = tid >> 5;
    const int lane = tid & 31;
    const int m0 = (w & 1) * 16;
    const int n0 = (w >> 1) * 32;
    const int gid = lane >> 2;             // 0..7
    const int tig = lane & 3;              // 0..3

    float c[4][4];
#pragma unroll
    for (int i = 0; i < 4; i++)
#pragma unroll
        for (int j = 0; j < 4; j++) c[i][j] = 0.f;

    const float4* p4 = (const float4*)proj_w;
    const float4* f4 = (const float4*)g_feats;

    for (int kt = 0; kt < 128; kt += 32) {
        const int k0 = k0base + kt;
        {
            int kk = tid >> 3, m4 = tid & 7;
            float4 v = f4[((b << 10) + k0 + kk) * 256 + t04 + m4];
            uint32_t* dst = &As[kk * 40 + m4 * 4];
            dst[0] = f2tf32(v.x); dst[1] = f2tf32(v.y);
            dst[2] = f2tf32(v.z); dst[3] = f2tf32(v.w);
        }
#pragma unroll
        for (int r = 0; r < 4; r++) {
            int idx = tid + r * 256;
            int kk = idx >> 5, n4 = idx & 31;
            float4 v = p4[(k0 + kk) * 32 + n4];
            uint32_t* dst = &Bs[kk * 136 + n4 * 4];
            dst[0] = f2tf32(v.x); dst[1] = f2tf32(v.y);
            dst[2] = f2tf32(v.z); dst[3] = f2tf32(v.w);
        }
        __syncthreads();
#pragma unroll
        for (int k8 = 0; k8 < 32; k8 += 8) {
            uint32_t a0 = As[(k8 + tig) * 40 + m0 + gid];
            uint32_t a1 = As[(k8 + tig) * 40 + m0 + gid + 8];
            uint32_t a2 = As[(k8 + tig + 4) * 40 + m0 + gid];
            uint32_t a3 = As[(k8 + tig + 4) * 40 + m0 + gid + 8];
#pragma unroll
            for (int nf = 0; nf < 4; nf++) {
                int n = n0 + nf * 8 + gid;
                uint32_t b0 = Bs[(k8 + tig) * 136 + n];
                uint32_t b1 = Bs[(k8 + tig + 4) * 136 + n];
                mma_tf32(c[nf], a0, a1, a2, a3, b0, b1);
            }
        }
        __syncthreads();
    }
    float* dst = g_xpart[blockIdx.y];
#pragma unroll
    for (int nf = 0; nf < 4; nf++) {
        int col = n0 + nf * 8 + tig * 2;
        *(float2*)&dst[(gm0 + m0 + gid) * DD + col]     = make_float2(c[nf][0], c[nf][1]);
        *(float2*)&dst[(gm0 + m0 + gid + 8) * DD + col] = make_float2(c[nf][2], c[nf][3]);
    }
}

// ---------------------------------------------------------------------------
// K3: sum KSPLIT partials, L2-normalize each 128-dim row. Warp per row.
// ---------------------------------------------------------------------------
__global__ void __launch_bounds__(128) norm_kernel() {
    const int row = blockIdx.x * 4 + (threadIdx.x >> 5);   // 0..2047
    const int lane = threadIdx.x & 31;
    float4 v = make_float4(0.f, 0.f, 0.f, 0.f);
#pragma unroll
    for (int s = 0; s < KSPLIT; s++) {
        float4 p = ((const float4*)g_xpart[s])[row * 32 + lane];
        v.x += p.x; v.y += p.y; v.z += p.z; v.w += p.w;
    }
    float sq = v.x * v.x + v.y * v.y + v.z * v.z + v.w * v.w;
#pragma unroll
    for (int o = 16; o; o >>= 1) sq += __shfl_xor_sync(0xFFFFFFFFu, sq, o);
    const float inv = 1.0f / fmaxf(sqrtf(sq), 1e-12f);
    ((float4*)g_xnorm)[row * 32 + lane] =
        make_float4(v.x * inv, v.y * inv, v.z * inv, v.w * inv);
}

// ---------------------------------------------------------------------------
// K4: banded cosine similarity, diagonal-parameterized, 256 threads/block.
// grid (128, 2): bx -> 16 t's, by -> j-half.  Thread = 1 t x 5 s-rows.
// ---------------------------------------------------------------------------
__global__ void __launch_bounds__(256) band_kernel() {
    __shared__ ulonglong2 xs[66 * 33];    // 66 rows x (32 float4 + pad)
    const int tid = threadIdx.x;
    const int gt0 = blockIdx.x * 16;
    const int b = gt0 >> 10;
    const int t0 = gt0 & 1023;
    const int by = blockIdx.y;
    const int s0 = by ? t0 : t0 - W2;     // staged global row base

    const ulonglong2* xn2 = (const ulonglong2*)g_xnorm;
#pragma unroll
    for (int i = 0; i < 9; i++) {
        int idx = tid + i * 256;
        if (idx < 66 * 32) {
            int r = idx >> 5, q = idx & 31;
            int s = s0 + r;
            ulonglong2 v; v.x = 0ull; v.y = 0ull;
            if (s >= 0 && s < TT) v = xn2[((b << 10) + s) * 32 + q];
            xs[r * 33 + q] = v;
        }
    }
    __syncthreads();

    const int tl = tid >> 4;              // t_local 0..15
    const int sg = tid & 15;              // s_idx = sg + ss*16, ss in 0..4
    const int ra = (by ? 0 : W2) + tl;    // staged idx of a-row

    unsigned long long acc[5] = {0ull, 0ull, 0ull, 0ull, 0ull};

    int srow[5];
#pragma unroll
    for (int ss = 0; ss < 5; ss++) {
        int si = sg + ss * 16;
        srow[ss] = (si < 66 ? si : 65);   // clamp; masked at write
    }

#pragma unroll 8
    for (int q = 0; q < 32; q++) {
        ulonglong2 a = xs[ra * 33 + q];
#pragma unroll
        for (int ss = 0; ss < 5; ss++) {
            ulonglong2 bv = xs[srow[ss] * 33 + q];
            fma2(acc[ss], a.x, bv.x);
            fma2(acc[ss], a.y, bv.y);
        }
    }

#pragma unroll
    for (int ss = 0; ss < 5; ss++) {
        int si = sg + ss * 16;
        int d = si - tl;                  // j (half 0) or j-50 (half 1)
        bool ok = by ? (d >= 1 && d <= 50) : (d >= 0 && d <= 50);
        if (ok && si < 66) {
            int j = by ? d + W2 : d;
            float2 p = unpack2(acc[ss]);
            g_band[(gt0 + tl) * LL + j] = p.x + p.y;
        }
    }
}

// ---------------------------------------------------------------------------
// K5: out = relu(band @ fc_w + fc_b).
// grid (128, 2): bx -> 16 t rows, by -> 64-d half.
// ---------------------------------------------------------------------------
__global__ void __launch_bounds__(256) fc_kernel(const float* __restrict__ fc_w,
                                                 const float* __restrict__ fc_b,
                                                 float* __restrict__ out) {
    __shared__ float As[16 * LL];
    __shared__ float4 Bs[LL * 17];
    const int tid = threadIdx.x;
    const int gt0 = blockIdx.x * 16;
    const int h = blockIdx.y;

#pragma unroll
    for (int i = 0; i < 7; i++) {
        int idx = tid + i * 256;
        if (idx < 16 * LL) As[idx] = g_band[gt0 * LL + idx];
    }
#pragma unroll
    for (int i = 0; i < 7; i++) {
        int idx = tid + i * 256;
        if (idx < LL * 16) {
            int k = idx >> 4, q = idx & 15;
            Bs[k * 17 + q] = ((const float4*)fc_w)[k * 32 + h * 16 + q];
        }
    }
    __syncthreads();

    const int tl = tid >> 4;
    const int dg = tid & 15;

    unsigned long long acc0 = 0ull, acc1 = 0ull;
    const float* arow = &As[tl * LL];
#pragma unroll 4
    for (int k = 0; k < LL; k++) {
        unsigned long long ap = pack2(arow[k], arow[k]);
        ulonglong2 b2 = *(const ulonglong2*)&Bs[k * 17 + dg];
        fma2(acc0, ap, b2.x);
        fma2(acc1, ap, b2.y);
    }
    float2 r0 = unpack2(acc0);
    float2 r1 = unpack2(acc1);
    float4 bias = ((const float4*)fc_b)[h * 16 + dg];
    float4 o;
    o.x = fmaxf(r0.x + bias.x, 0.f);
    o.y = fmaxf(r0.y + bias.y, 0.f);
    o.z = fmaxf(r1.x + bias.z, 0.f);
    o.w = fmaxf(r1.y + bias.w, 0.f);
    ((float4*)out)[(gt0 + tl) * 32 + h * 16 + dg] = o;
}

// ---------------------------------------------------------------------------
extern "C" void kernel_launch(void* const* d_in, const int* in_sizes, int n_in,
                              void* d_out, int out_size) {
    const float* x0     = (const float*)d_in[0];
    const float* x1     = (const float*)d_in[1];
    const float* proj_w = (const float*)d_in[2];
    const float* fc_w   = (const float*)d_in[3];
    const float* fc_b   = (const float*)d_in[4];
    float* out = (float*)d_out;

    pool_kernel<<<2048, 32>>>(x0, x1);
    gemm_proj_kernel<<<dim3(64, KSPLIT), 256>>>(proj_w);
    norm_kernel<<<512, 128>>>();
    band_kernel<<<dim3(128, 2), 256>>>();
    fc_kernel<<<dim3(128, 2), 256>>>(fc_w, fc_b, out);
}

// round 8
// speedup vs baseline: 1.3063x; 1.0247x over previous
#include <cuda_runtime.h>
#include <cstdint>

// Problem constants
#define BB 2
#define C0 512
#define CT 1024        // total channels
#define TT 1024        // time
#define HW 49          // 7*7
#define DD 128         // SIM_DIM / OUT_DIM
#define LL 101         // LOOKUP
#define W2 50

#define KSPLIT 8

// Scratch (device globals: allowed; no runtime allocation)
__device__ float g_feats[BB * CT * TT];               // [b][c][t]  8 MB
__device__ float g_xpart[KSPLIT][BB * TT * DD];       // k-split partials
__device__ float g_xnorm[BB * TT * DD];               // normalized rows, 1 MB
__device__ float g_band[BB * TT * LL];                // banded sims, 827 KB

// ---- packed fp32x2 helpers (Blackwell) ------------------------------------
__device__ __forceinline__ void fma2(unsigned long long& acc,
                                     unsigned long long a, unsigned long long b) {
    asm("fma.rn.f32x2 %0, %1, %2, %0;" : "+l"(acc) : "l"(a), "l"(b));
}
__device__ __forceinline__ unsigned long long pack2(float x, float y) {
    unsigned long long r;
    asm("mov.b64 %0, {%1, %2};" : "=l"(r) : "f"(x), "f"(y));
    return r;
}
__device__ __forceinline__ float2 unpack2(unsigned long long v) {
    float2 f;
    asm("mov.b64 {%0, %1}, %2;" : "=f"(f.x), "=f"(f.y) : "l"(v));
    return f;
}
__device__ __forceinline__ uint32_t f2tf32(float x) {
    uint32_t r;
    asm("cvt.rna.tf32.f32 %0, %1;" : "=r"(r) : "f"(x));
    return r;
}
__device__ __forceinline__ void mma_tf32(float c[4], uint32_t a0, uint32_t a1,
                                         uint32_t a2, uint32_t a3,
                                         uint32_t b0, uint32_t b1) {
    asm("mma.sync.aligned.m16n8k8.row.col.f32.tf32.tf32.f32 "
        "{%0,%1,%2,%3}, {%4,%5,%6,%7}, {%8,%9}, {%0,%1,%2,%3};"
        : "+f"(c[0]), "+f"(c[1]), "+f"(c[2]), "+f"(c[3])
        : "r"(a0), "r"(a1), "r"(a2), "r"(a3), "r"(b0), "r"(b1));
}

// ---- cp.async helpers ------------------------------------------------------
__device__ __forceinline__ void cpasync16(uint32_t s, const void* g) {
    asm volatile("cp.async.cg.shared.global [%0], [%1], 16;" :: "r"(s), "l"(g));
}
__device__ __forceinline__ void cp_commit() {
    asm volatile("cp.async.commit_group;");
}
template <int N> __device__ __forceinline__ void cp_wait() {
    asm volatile("cp.async.wait_group %0;" :: "n"(N));
}

// ---------------------------------------------------------------------------
// K1: spatial mean pool — channel-streaming warps + cp.async double buffering.
// One warp per block (12.5 KB smem), single wave of 2048 blocks.
// ---------------------------------------------------------------------------
__global__ void __launch_bounds__(32) pool_kernel(const float* __restrict__ x0,
                                                  const float* __restrict__ x1) {
    __shared__ float sm[2][1568];
    const int lane = threadIdx.x;
    const int ch = blockIdx.x;             // 0..2047
    const int b = ch >> 10;
    const int c = ch & 1023;

    const float* src = (c < C0)
        ? x0 + (size_t)(b * C0 + c) * TT * HW
        : x1 + (size_t)(b * C0 + (c - C0)) * TT * HW;

    uint32_t sb[2];
    sb[0] = (uint32_t)__cvta_generic_to_shared(&sm[0][0]);
    sb[1] = (uint32_t)__cvta_generic_to_shared(&sm[1][0]);

    auto issue = [&](int k, int buf) {
        const float4* g = (const float4*)(src + (size_t)k * 1568);
        uint32_t s = sb[buf];
#pragma unroll
        for (int i = 0; i < 12; i++)
            cpasync16(s + (i * 32 + lane) * 16, g + i * 32 + lane);
        if (lane < 8)
            cpasync16(s + (384 + lane) * 16, g + 384 + lane);
        cp_commit();
    };

    issue(0, 0);
    issue(1, 1);

    float* dst = &g_feats[(size_t)ch * TT];

    for (int k = 0; k < 32; k++) {
        if (k < 31) cp_wait<1>(); else cp_wait<0>();
        __syncwarp();
        const float* row = &sm[k & 1][lane * 49];
        float s = 0.f;
#pragma unroll
        for (int j = 0; j < 49; j++) s += row[j];
        dst[k * 32 + lane] = s * (1.0f / 49.0f);
        __syncwarp();
        if (k + 2 < 32) issue(k + 2, k & 1);
    }
}

// ---------------------------------------------------------------------------
// K2: projection GEMM with TF32 mma.sync (m16n8k8).
// Block: M=32 x N=128 x K=128, 256 threads.  KSPLIT=8 -> grid (64,8)=512.
// ---------------------------------------------------------------------------
__global__ void __launch_bounds__(256) gemm_proj_kernel(const float* __restrict__ proj_w) {
    __shared__ uint32_t As[32 * 40];       // [k][m] tf32
    __shared__ uint32_t Bs[32 * 136];      // [k][n] tf32
    const int tid = threadIdx.x;
    const int gm0 = blockIdx.x * 32;       // global row base (b*T + t)
    const int b = gm0 >> 10;
    const int t04 = (gm0 & 1023) >> 2;
    const int k0base = blockIdx.y * 128;

    const int w = tid >> 5;
    const int lane = tid & 31;
    const int m0 = (w & 1) * 16;
    const int n0 = (w >> 1) * 32;
    const int gid = lane >> 2;             // 0..7
    const int tig = lane & 3;              // 0..3

    float c[4][4];
#pragma unroll
    for (int i = 0; i < 4; i++)
#pragma unroll
        for (int j = 0; j < 4; j++) c[i][j] = 0.f;

    const float4* p4 = (const float4*)proj_w;
    const float4* f4 = (const float4*)g_feats;

    for (int kt = 0; kt < 128; kt += 32) {
        const int k0 = k0base + kt;
        {
            int kk = tid >> 3, m4 = tid & 7;
            float4 v = f4[((b << 10) + k0 + kk) * 256 + t04 + m4];
            uint32_t* dst = &As[kk * 40 + m4 * 4];
            dst[0] = f2tf32(v.x); dst[1] = f2tf32(v.y);
            dst[2] = f2tf32(v.z); dst[3] = f2tf32(v.w);
        }
#pragma unroll
        for (int r = 0; r < 4; r++) {
            int idx = tid + r * 256;
            int kk = idx >> 5, n4 = idx & 31;
            float4 v = p4[(k0 + kk) * 32 + n4];
            uint32_t* dst = &Bs[kk * 136 + n4 * 4];
            dst[0] = f2tf32(v.x); dst[1] = f2tf32(v.y);
            dst[2] = f2tf32(v.z); dst[3] = f2tf32(v.w);
        }
        __syncthreads();
#pragma unroll
        for (int k8 = 0; k8 < 32; k8 += 8) {
            uint32_t a0 = As[(k8 + tig) * 40 + m0 + gid];
            uint32_t a1 = As[(k8 + tig) * 40 + m0 + gid + 8];
            uint32_t a2 = As[(k8 + tig + 4) * 40 + m0 + gid];
            uint32_t a3 = As[(k8 + tig + 4) * 40 + m0 + gid + 8];
#pragma unroll
            for (int nf = 0; nf < 4; nf++) {
                int n = n0 + nf * 8 + gid;
                uint32_t b0 = Bs[(k8 + tig) * 136 + n];
                uint32_t b1 = Bs[(k8 + tig + 4) * 136 + n];
                mma_tf32(c[nf], a0, a1, a2, a3, b0, b1);
            }
        }
        __syncthreads();
    }
    float* dst = g_xpart[blockIdx.y];
#pragma unroll
    for (int nf = 0; nf < 4; nf++) {
        int col = n0 + nf * 8 + tig * 2;
        *(float2*)&dst[(gm0 + m0 + gid) * DD + col]     = make_float2(c[nf][0], c[nf][1]);
        *(float2*)&dst[(gm0 + m0 + gid + 8) * DD + col] = make_float2(c[nf][2], c[nf][3]);
    }
}

// ---------------------------------------------------------------------------
// K3: sum KSPLIT partials, L2-normalize each 128-dim row. Warp per row.
// ---------------------------------------------------------------------------
__global__ void __launch_bounds__(128) norm_kernel() {
    const int row = blockIdx.x * 4 + (threadIdx.x >> 5);   // 0..2047
    const int lane = threadIdx.x & 31;
    float4 v = make_float4(0.f, 0.f, 0.f, 0.f);
#pragma unroll
    for (int s = 0; s < KSPLIT; s++) {
        float4 p = ((const float4*)g_xpart[s])[row * 32 + lane];
        v.x += p.x; v.y += p.y; v.z += p.z; v.w += p.w;
    }
    float sq = v.x * v.x + v.y * v.y + v.z * v.z + v.w * v.w;
#pragma unroll
    for (int o = 16; o; o >>= 1) sq += __shfl_xor_sync(0xFFFFFFFFu, sq, o);
    const float inv = 1.0f / fmaxf(sqrtf(sq), 1e-12f);
    ((float4*)g_xnorm)[row * 32 + lane] =
        make_float4(v.x * inv, v.y * inv, v.z * inv, v.w * inv);
}

// ---------------------------------------------------------------------------
// K4: banded cosine similarity via TF32 tensor cores.
// grid (128, 2): bx -> 16 t rows, by -> 64-s-column half of the staged window.
// Per block: A16 = xnorm[t0..t0+15], B64 = xnorm[t0-50+by*64 .. +63] (zeros
// outside [0,T) == reference zero-padding).  Two 64-dim k-passes; smem stride
// 68 makes every fragment LDS land on bank (4*gid+tig) = lane -> conflict-free.
// C[16 x 64] scattered to g_band at j = by*64 + s_local - tl, masked 0..100.
// Each (t,j) is produced by exactly one block (s_idx = j + tl is unique).
// ---------------------------------------------------------------------------
__global__ void __launch_bounds__(256) band_kernel() {
    __shared__ uint32_t Asm[16 * 68];      // 16 t-rows x 64 dims (tf32, pad 4)
    __shared__ uint32_t Bsm[64 * 68];      // 64 s-rows x 64 dims
    const int tid = threadIdx.x;
    const int gt0 = blockIdx.x * 16;
    const int b = gt0 >> 10;
    const int t0 = gt0 & 1023;
    const int by = blockIdx.y;
    const int sbase = t0 - W2 + by * 64;   // global s of B row 0

    const int w = tid >> 5;                // warp 0..7 -> n-tile w (8 s-cols)
    const int lane = tid & 31;
    const int gid = lane >> 2;             // 0..7
    const int tig = lane & 3;              // 0..3

    float ce[4] = {0.f, 0.f, 0.f, 0.f};    // even k8 accumulator
    float co[4] = {0.f, 0.f, 0.f, 0.f};    // odd  k8 accumulator

    const float4* xn4 = (const float4*)g_xnorm;

    for (int p = 0; p < 2; p++) {
        __syncthreads();
        // stage A: 16 rows x 16 float4 (one per thread)
        {
            int r = tid >> 4, q = tid & 15;
            float4 v = xn4[((b << 10) + t0 + r) * 32 + p * 16 + q];
            uint32_t* d = &Asm[r * 68 + q * 4];
            d[0] = f2tf32(v.x); d[1] = f2tf32(v.y);
            d[2] = f2tf32(v.z); d[3] = f2tf32(v.w);
        }
        // stage B: 64 rows x 16 float4 (four per thread), zero outside [0,T)
#pragma unroll
        for (int i = 0; i < 4; i++) {
            int idx = tid + i * 256;
            int r = idx >> 4, q = idx & 15;
            int s = sbase + r;
            float4 v = make_float4(0.f, 0.f, 0.f, 0.f);
            if (s >= 0 && s < TT) v = xn4[((b << 10) + s) * 32 + p * 16 + q];
            uint32_t* d = &Bsm[r * 68 + q * 4];
            d[0] = f2tf32(v.x); d[1] = f2tf32(v.y);
            d[2] = f2tf32(v.z); d[3] = f2tf32(v.w);
        }
        __syncthreads();
#pragma unroll
        for (int k8 = 0; k8 < 64; k8 += 16) {
            // even k8
            {
                uint32_t a0 = Asm[gid * 68 + k8 + tig];
                uint32_t a1 = Asm[(gid + 8) * 68 + k8 + tig];
                uint32_t a2 = Asm[gid * 68 + k8 + tig + 4];
                uint32_t a3 = Asm[(gid + 8) * 68 + k8 + tig + 4];
                uint32_t b0 = Bsm[(w * 8 + gid) * 68 + k8 + tig];
                uint32_t b1 = Bsm[(w * 8 + gid) * 68 + k8 + tig + 4];
                mma_tf32(ce, a0, a1, a2, a3, b0, b1);
            }
            // odd k8
            {
                int k = k8 + 8;
                uint32_t a0 = Asm[gid * 68 + k + tig];
                uint32_t a1 = Asm[(gid + 8) * 68 + k + tig];
                uint32_t a2 = Asm[gid * 68 + k + tig + 4];
                uint32_t a3 = Asm[(gid + 8) * 68 + k + tig + 4];
                uint32_t b0 = Bsm[(w * 8 + gid) * 68 + k + tig];
                uint32_t b1 = Bsm[(w * 8 + gid) * 68 + k + tig + 4];
                mma_tf32(co, a0, a1, a2, a3, b0, b1);
            }
        }
    }

    // epilogue: scatter banded entries
    const int scol = w * 8 + tig * 2;      // block-local s of c[0]/c[2]
#pragma unroll
    for (int h = 0; h < 2; h++) {
        int tl = gid + h * 8;
        int j0 = by * 64 + scol - tl;
        float v0 = ce[h * 2 + 0] + co[h * 2 + 0];
        float v1 = ce[h * 2 + 1] + co[h * 2 + 1];
        float* dst = &g_band[(gt0 + tl) * LL];
        if (j0 >= 0 && j0 <= 100) dst[j0] = v0;
        if (j0 + 1 >= 0 && j0 + 1 <= 100) dst[j0 + 1] = v1;
    }
}

// ---------------------------------------------------------------------------
// K5: out = relu(band @ fc_w + fc_b).
// grid (128, 2): bx -> 16 t rows, by -> 64-d half.
// ---------------------------------------------------------------------------
__global__ void __launch_bounds__(256) fc_kernel(const float* __restrict__ fc_w,
                                                 const float* __restrict__ fc_b,
                                                 float* __restrict__ out) {
    __shared__ float As[16 * LL];
    __shared__ float4 Bs[LL * 17];
    const int tid = threadIdx.x;
    const int gt0 = blockIdx.x * 16;
    const int h = blockIdx.y;

#pragma unroll
    for (int i = 0; i < 7; i++) {
        int idx = tid + i * 256;
        if (idx < 16 * LL) As[idx] = g_band[gt0 * LL + idx];
    }
#pragma unroll
    for (int i = 0; i < 7; i++) {
        int idx = tid + i * 256;
        if (idx < LL * 16) {
            int k = idx >> 4, q = idx & 15;
            Bs[k * 17 + q] = ((const float4*)fc_w)[k * 32 + h * 16 + q];
        }
    }
    __syncthreads();

    const int tl = tid >> 4;
    const int dg = tid & 15;

    unsigned long long acc0 = 0ull, acc1 = 0ull;
    const float* arow = &As[tl * LL];
#pragma unroll 4
    for (int k = 0; k < LL; k++) {
        unsigned long long ap = pack2(arow[k], arow[k]);
        ulonglong2 b2 = *(const ulonglong2*)&Bs[k * 17 + dg];
        fma2(acc0, ap, b2.x);
        fma2(acc1, ap, b2.y);
    }
    float2 r0 = unpack2(acc0);
    float2 r1 = unpack2(acc1);
    float4 bias = ((const float4*)fc_b)[h * 16 + dg];
    float4 o;
    o.x = fmaxf(r0.x + bias.x, 0.f);
    o.y = fmaxf(r0.y + bias.y, 0.f);
    o.z = fmaxf(r1.x + bias.z, 0.f);
    o.w = fmaxf(r1.y + bias.w, 0.f);
    ((float4*)out)[(gt0 + tl) * 32 + h * 16 + dg] = o;
}

// ---------------------------------------------------------------------------
extern "C" void kernel_launch(void* const* d_in, const int* in_sizes, int n_in,
                              void* d_out, int out_size) {
    const float* x0     = (const float*)d_in[0];
    const float* x1     = (const float*)d_in[1];
    const float* proj_w = (const float*)d_in[2];
    const float* fc_w   = (const float*)d_in[3];
    const float* fc_b   = (const float*)d_in[4];
    float* out = (float*)d_out;

    pool_kernel<<<2048, 32>>>(x0, x1);
    gemm_proj_kernel<<<dim3(64, KSPLIT), 256>>>(proj_w);
    norm_kernel<<<512, 128>>>();
    band_kernel<<<dim3(128, 2), 256>>>();
    fc_kernel<<<dim3(128, 2), 256>>>(fc_w, fc_b, out);
}

// round 10
// speedup vs baseline: 1.3444x; 1.0291x over previous
#include <cuda_runtime.h>
#include <cstdint>

// Problem constants
#define BB 2
#define C0 512
#define CT 1024        // total channels
#define TT 1024        // time
#define HW 49          // 7*7
#define DD 128         // SIM_DIM / OUT_DIM
#define LL 101         // LOOKUP
#define W2 50

#define KSPLIT 8

// Scratch (device globals: allowed; no runtime allocation)
__device__ float g_feats[BB * CT * TT];               // [b][c][t]  8 MB
__device__ float g_xpart[KSPLIT][BB * TT * DD];       // k-split partials
__device__ float g_xnorm[BB * TT * DD];               // normalized rows, 1 MB

// ---- packed fp32x2 helpers (Blackwell) ------------------------------------
__device__ __forceinline__ void fma2(unsigned long long& acc,
                                     unsigned long long a, unsigned long long b) {
    asm("fma.rn.f32x2 %0, %1, %2, %0;" : "+l"(acc) : "l"(a), "l"(b));
}
__device__ __forceinline__ unsigned long long pack2(float x, float y) {
    unsigned long long r;
    asm("mov.b64 %0, {%1, %2};" : "=l"(r) : "f"(x), "f"(y));
    return r;
}
__device__ __forceinline__ float2 unpack2(unsigned long long v) {
    float2 f;
    asm("mov.b64 {%0, %1}, %2;" : "=f"(f.x), "=f"(f.y) : "l"(v));
    return f;
}
__device__ __forceinline__ uint32_t f2tf32(float x) {
    uint32_t r;
    asm("cvt.rna.tf32.f32 %0, %1;" : "=r"(r) : "f"(x));
    return r;
}
__device__ __forceinline__ void mma_tf32(float c[4], uint32_t a0, uint32_t a1,
                                         uint32_t a2, uint32_t a3,
                                         uint32_t b0, uint32_t b1) {
    asm("mma.sync.aligned.m16n8k8.row.col.f32.tf32.tf32.f32 "
        "{%0,%1,%2,%3}, {%4,%5,%6,%7}, {%8,%9}, {%0,%1,%2,%3};"
        : "+f"(c[0]), "+f"(c[1]), "+f"(c[2]), "+f"(c[3])
        : "r"(a0), "r"(a1), "r"(a2), "r"(a3), "r"(b0), "r"(b1));
}

// ---- cp.async helpers ------------------------------------------------------
__device__ __forceinline__ void cpasync16(uint32_t s, const void* g) {
    asm volatile("cp.async.cg.shared.global [%0], [%1], 16;" :: "r"(s), "l"(g));
}
__device__ __forceinline__ void cp_commit() {
    asm volatile("cp.async.commit_group;");
}
template <int N> __device__ __forceinline__ void cp_wait() {
    asm volatile("cp.async.wait_group %0;" :: "n"(N));
}

// ---------------------------------------------------------------------------
// K1: spatial mean pool — channel-streaming warps + cp.async double buffering.
// One warp per block (12.5 KB smem), single wave of 2048 blocks.
// ---------------------------------------------------------------------------
__global__ void __launch_bounds__(32) pool_kernel(const float* __restrict__ x0,
                                                  const float* __restrict__ x1) {
    __shared__ float sm[2][1568];
    const int lane = threadIdx.x;
    const int ch = blockIdx.x;             // 0..2047
    const int b = ch >> 10;
    const int c = ch & 1023;

    const float* src = (c < C0)
        ? x0 + (size_t)(b * C0 + c) * TT * HW
        : x1 + (size_t)(b * C0 + (c - C0)) * TT * HW;

    uint32_t sb[2];
    sb[0] = (uint32_t)__cvta_generic_to_shared(&sm[0][0]);
    sb[1] = (uint32_t)__cvta_generic_to_shared(&sm[1][0]);

    auto issue = [&](int k, int buf) {
        const float4* g = (const float4*)(src + (size_t)k * 1568);
        uint32_t s = sb[buf];
#pragma unroll
        for (int i = 0; i < 12; i++)
            cpasync16(s + (i * 32 + lane) * 16, g + i * 32 + lane);
        if (lane < 8)
            cpasync16(s + (384 + lane) * 16, g + 384 + lane);
        cp_commit();
    };

    issue(0, 0);
    issue(1, 1);

    float* dst = &g_feats[(size_t)ch * TT];

    for (int k = 0; k < 32; k++) {
        if (k < 31) cp_wait<1>(); else cp_wait<0>();
        __syncwarp();
        const float* row = &sm[k & 1][lane * 49];
        float s = 0.f;
#pragma unroll
        for (int j = 0; j < 49; j++) s += row[j];
        dst[k * 32 + lane] = s * (1.0f / 49.0f);
        __syncwarp();
        if (k + 2 < 32) issue(k + 2, k & 1);
    }
}

// ---------------------------------------------------------------------------
// K2: projection GEMM with TF32 mma.sync (m16n8k8).
// Block: M=32 x N=128 x K=128, 256 threads.  KSPLIT=8 -> grid (64,8)=512.
// ---------------------------------------------------------------------------
__global__ void __launch_bounds__(256) gemm_proj_kernel(const float* __restrict__ proj_w) {
    __shared__ uint32_t As[32 * 40];       // [k][m] tf32
    __shared__ uint32_t Bs[32 * 136];      // [k][n] tf32
    const int tid = threadIdx.x;
    const int gm0 = blockIdx.x * 32;       // global row base (b*T + t)
    const int b = gm0 >> 10;
    const int t04 = (gm0 & 1023) >> 2;
    const int k0base = blockIdx.y * 128;

    const int w = tid >> 5;
    const int lane = tid & 31;
    const int m0 = (w & 1) * 16;
    const int n0 = (w >> 1) * 32;
    const int gid = lane >> 2;             // 0..7
    const int tig = lane & 3;              // 0..3

    float c[4][4];
#pragma unroll
    for (int i = 0; i < 4; i++)
#pragma unroll
        for (int j = 0; j < 4; j++) c[i][j] = 0.f;

    const float4* p4 = (const float4*)proj_w;
    const float4* f4 = (const float4*)g_feats;

    for (int kt = 0; kt < 128; kt += 32) {
        const int k0 = k0base + kt;
        {
            int kk = tid >> 3, m4 = tid & 7;
            float4 v = f4[((b << 10) + k0 + kk) * 256 + t04 + m4];
            uint32_t* dst = &As[kk * 40 + m4 * 4];
            dst[0] = f2tf32(v.x); dst[1] = f2tf32(v.y);
            dst[2] = f2tf32(v.z); dst[3] = f2tf32(v.w);
        }
#pragma unroll
        for (int r = 0; r < 4; r++) {
            int idx = tid + r * 256;
            int kk = idx >> 5, n4 = idx & 31;
            float4 v = p4[(k0 + kk) * 32 + n4];
            uint32_t* dst = &Bs[kk * 136 + n4 * 4];
            dst[0] = f2tf32(v.x); dst[1] = f2tf32(v.y);
            dst[2] = f2tf32(v.z); dst[3] = f2tf32(v.w);
        }
        __syncthreads();
#pragma unroll
        for (int k8 = 0; k8 < 32; k8 += 8) {
            uint32_t a0 = As[(k8 + tig) * 40 + m0 + gid];
            uint32_t a1 = As[(k8 + tig) * 40 + m0 + gid + 8];
            uint32_t a2 = As[(k8 + tig + 4) * 40 + m0 + gid];
            uint32_t a3 = As[(k8 + tig + 4) * 40 + m0 + gid + 8];
#pragma unroll
            for (int nf = 0; nf < 4; nf++) {
                int n = n0 + nf * 8 + gid;
                uint32_t b0 = Bs[(k8 + tig) * 136 + n];
                uint32_t b1 = Bs[(k8 + tig + 4) * 136 + n];
                mma_tf32(c[nf], a0, a1, a2, a3, b0, b1);
            }
        }
        __syncthreads();
    }
    float* dst = g_xpart[blockIdx.y];
#pragma unroll
    for (int nf = 0; nf < 4; nf++) {
        int col = n0 + nf * 8 + tig * 2;
        *(float2*)&dst[(gm0 + m0 + gid) * DD + col]     = make_float2(c[nf][0], c[nf][1]);
        *(float2*)&dst[(gm0 + m0 + gid + 8) * DD + col] = make_float2(c[nf][2], c[nf][3]);
    }
}

// ---------------------------------------------------------------------------
// K3: sum KSPLIT partials, L2-normalize each 128-dim row. Warp per row.
// ---------------------------------------------------------------------------
__global__ void __launch_bounds__(128) norm_kernel() {
    const int row = blockIdx.x * 4 + (threadIdx.x >> 5);   // 0..2047
    const int lane = threadIdx.x & 31;
    float4 v = make_float4(0.f, 0.f, 0.f, 0.f);
#pragma unroll
    for (int s = 0; s < KSPLIT; s++) {
        float4 p = ((const float4*)g_xpart[s])[row * 32 + lane];
        v.x += p.x; v.y += p.y; v.z += p.z; v.w += p.w;
    }
    float sq = v.x * v.x + v.y * v.y + v.z * v.z + v.w * v.w;
#pragma unroll
    for (int o = 16; o; o >>= 1) sq += __shfl_xor_sync(0xFFFFFFFFu, sq, o);
    const float inv = 1.0f / fmaxf(sqrtf(sq), 1e-12f);
    ((float4*)g_xnorm)[row * 32 + lane] =
        make_float4(v.x * inv, v.y * inv, v.z * inv, v.w * inv);
}

// ---------------------------------------------------------------------------
// K4: fused banded similarity (TF32 MMA) + fc + bias + relu.
// grid 128: block = 16 t rows.  Stage s-window of 128 rows (t0-50..t0+77,
// zeros outside [0,T) == reference zero padding) in two 64-dim k-passes.
// MMA m16 x n128 x k128 -> C[tl][n] = sim(t0+tl, t0-50+n); scatter into smem
// band tile at j = n - tl (each (t,j) exactly once, n = tl+j in [0,115]).
// Then fc in fp32 fma2 from smem, fc_w staged into the retired B region.
// ---------------------------------------------------------------------------
__global__ void __launch_bounds__(256) bandfc_kernel(const float* __restrict__ fc_w,
                                                     const float* __restrict__ fc_b,
                                                     float* __restrict__ out) {
    __shared__ uint32_t Asm[16 * 68];      // 16 t-rows x 64 dims (tf32, pad 4)
    __shared__ uint32_t Bsm[128 * 68];     // 128 s-rows x 64 dims; reused for fc_w
    __shared__ float band_sm[16 * 104];    // [tl][j] banded sims (j 0..100)

    const int tid = threadIdx.x;
    const int gt0 = blockIdx.x * 16;
    const int b = gt0 >> 10;
    const int t0 = gt0 & 1023;
    const int sbase = t0 - W2;             // global s of B row 0

    const int w = tid >> 5;                // warp 0..7
    const int lane = tid & 31;
    const int gid = lane >> 2;             // 0..7
    const int tig = lane & 3;              // 0..3

    float acc[2][4];                       // [n-tile 0: n=w*8.., 1: n=64+w*8..]
#pragma unroll
    for (int nt = 0; nt < 2; nt++)
#pragma unroll
        for (int i = 0; i < 4; i++) acc[nt][i] = 0.f;

    const float4* xn4 = (const float4*)g_xnorm;

    for (int p = 0; p < 2; p++) {
        __syncthreads();
        // stage A: 16 rows x 16 float4 (one per thread)
        {
            int r = tid >> 4, q = tid & 15;
            float4 v = xn4[((b << 10) + t0 + r) * 32 + p * 16 + q];
            uint32_t* d = &Asm[r * 68 + q * 4];
            d[0] = f2tf32(v.x); d[1] = f2tf32(v.y);
            d[2] = f2tf32(v.z); d[3] = f2tf32(v.w);
        }
        // stage B: 128 rows x 16 float4 (eight per thread), zeros outside [0,T)
#pragma unroll
        for (int i = 0; i < 8; i++) {
            int idx = tid + i * 256;
            int r = idx >> 4, q = idx & 15;
            int s = sbase + r;
            float4 v = make_float4(0.f, 0.f, 0.f, 0.f);
            if (s >= 0 && s < TT) v = xn4[((b << 10) + s) * 32 + p * 16 + q];
            uint32_t* d = &Bsm[r * 68 + q * 4];
            d[0] = f2tf32(v.x); d[1] = f2tf32(v.y);
            d[2] = f2tf32(v.z); d[3] = f2tf32(v.w);
        }
        __syncthreads();
#pragma unroll
        for (int k8 = 0; k8 < 64; k8 += 8) {
            uint32_t a0 = Asm[gid * 68 + k8 + tig];
            uint32_t a1 = Asm[(gid + 8) * 68 + k8 + tig];
            uint32_t a2 = Asm[gid * 68 + k8 + tig + 4];
            uint32_t a3 = Asm[(gid + 8) * 68 + k8 + tig + 4];
#pragma unroll
            for (int nt = 0; nt < 2; nt++) {
                int nrow = nt * 64 + w * 8 + gid;
                uint32_t b0 = Bsm[nrow * 68 + k8 + tig];
                uint32_t b1 = Bsm[nrow * 68 + k8 + tig + 4];
                mma_tf32(acc[nt], a0, a1, a2, a3, b0, b1);
            }
        }
    }

    // scatter C into the smem band tile: j = n - tl
#pragma unroll
    for (int nt = 0; nt < 2; nt++) {
        int scol = nt * 64 + w * 8 + tig * 2;
#pragma unroll
        for (int h = 0; h < 2; h++) {
            int tl = gid + h * 8;
            int j0 = scol - tl;
            if (j0 >= 0 && j0 <= 100) band_sm[tl * 104 + j0] = acc[nt][h * 2 + 0];
            if (j0 + 1 >= 0 && j0 + 1 <= 100) band_sm[tl * 104 + j0 + 1] = acc[nt][h * 2 + 1];
        }
    }

    // fc: out = relu(band @ fc_w + fc_b), fp32 fma2, fc_w staged into Bsm region
    const int tl = tid >> 4;
    const int dg = tid & 15;
    float4* fcw = (float4*)Bsm;            // [101][17] float4, 27.5 KB <= region

    for (int h = 0; h < 2; h++) {
        __syncthreads();                   // MMA/scatter done (h=0) / reads done (h=1)
#pragma unroll
        for (int i = 0; i < 7; i++) {
            int idx = tid + i * 256;
            if (idx < LL * 16) {
                int k = idx >> 4, q = idx & 15;
                fcw[k * 17 + q] = ((const float4*)fc_w)[k * 32 + h * 16 + q];
            }
        }
        __syncthreads();

        unsigned long long acc0 = 0ull, acc1 = 0ull;
        const float* arow = &band_sm[tl * 104];
#pragma unroll 4
        for (int k = 0; k < LL; k++) {
            unsigned long long ap = pack2(arow[k], arow[k]);
            ulonglong2 b2 = *(const ulonglong2*)&fcw[k * 17 + dg];
            fma2(acc0, ap, b2.x);
            fma2(acc1, ap, b2.y);
        }
        float2 r0 = unpack2(acc0);
        float2 r1 = unpack2(acc1);
        float4 bias = ((const float4*)fc_b)[h * 16 + dg];
        float4 o;
        o.x = fmaxf(r0.x + bias.x, 0.f);
        o.y = fmaxf(r0.y + bias.y, 0.f);
        o.z = fmaxf(r1.x + bias.z, 0.f);
        o.w = fmaxf(r1.y + bias.w, 0.f);
        ((float4*)out)[(gt0 + tl) * 32 + h * 16 + dg] = o;
    }
}

// ---------------------------------------------------------------------------
extern "C" void kernel_launch(void* const* d_in, const int* in_sizes, int n_in,
                              void* d_out, int out_size) {
    const float* x0     = (const float*)d_in[0];
    const float* x1     = (const float*)d_in[1];
    const float* proj_w = (const float*)d_in[2];
    const float* fc_w   = (const float*)d_in[3];
    const float* fc_b   = (const float*)d_in[4];
    float* out = (float*)d_out;

    pool_kernel<<<2048, 32>>>(x0, x1);
    gemm_proj_kernel<<<dim3(64, KSPLIT), 256>>>(proj_w);
    norm_kernel<<<512, 128>>>();
    bandfc_kernel<<<128, 256>>>(fc_w, fc_b, out);
}

// round 11
// speedup vs baseline: 1.3617x; 1.0129x over previous
#include <cuda_runtime.h>
#include <cstdint>

// Problem constants
#define BB 2
#define C0 512
#define CT 1024        // total channels
#define TT 1024        // time
#define HW 49          // 7*7
#define DD 128         // SIM_DIM / OUT_DIM
#define LL 101         // LOOKUP
#define W2 50

#define KSPLIT 8

// Scratch (device globals: allowed; no runtime allocation)
__device__ float g_feats[BB * CT * TT];               // [b][c][t]  8 MB
__device__ float g_xpart[KSPLIT][BB * TT * DD];       // k-split partials
__device__ float g_xnorm[BB * TT * DD];               // normalized rows, 1 MB

// ---- packed fp32x2 helpers (Blackwell) ------------------------------------
__device__ __forceinline__ void fma2(unsigned long long& acc,
                                     unsigned long long a, unsigned long long b) {
    asm("fma.rn.f32x2 %0, %1, %2, %0;" : "+l"(acc) : "l"(a), "l"(b));
}
__device__ __forceinline__ unsigned long long pack2(float x, float y) {
    unsigned long long r;
    asm("mov.b64 %0, {%1, %2};" : "=l"(r) : "f"(x), "f"(y));
    return r;
}
__device__ __forceinline__ float2 unpack2(unsigned long long v) {
    float2 f;
    asm("mov.b64 {%0, %1}, %2;" : "=f"(f.x), "=f"(f.y) : "l"(v));
    return f;
}
__device__ __forceinline__ uint32_t f2tf32(float x) {
    uint32_t r;
    asm("cvt.rna.tf32.f32 %0, %1;" : "=r"(r) : "f"(x));
    return r;
}
__device__ __forceinline__ void mma_tf32(float c[4], uint32_t a0, uint32_t a1,
                                         uint32_t a2, uint32_t a3,
                                         uint32_t b0, uint32_t b1) {
    asm("mma.sync.aligned.m16n8k8.row.col.f32.tf32.tf32.f32 "
        "{%0,%1,%2,%3}, {%4,%5,%6,%7}, {%8,%9}, {%0,%1,%2,%3};"
        : "+f"(c[0]), "+f"(c[1]), "+f"(c[2]), "+f"(c[3])
        : "r"(a0), "r"(a1), "r"(a2), "r"(a3), "r"(b0), "r"(b1));
}

// ---- cp.async helpers ------------------------------------------------------
__device__ __forceinline__ void cpasync16(uint32_t s, const void* g) {
    asm volatile("cp.async.cg.shared.global [%0], [%1], 16;" :: "r"(s), "l"(g));
}
__device__ __forceinline__ void cp_commit() {
    asm volatile("cp.async.commit_group;");
}
template <int N> __device__ __forceinline__ void cp_wait() {
    asm volatile("cp.async.wait_group %0;" :: "n"(N));
}

// ---------------------------------------------------------------------------
// K1: spatial mean pool — channel-streaming warps + cp.async double buffering.
// One warp per block (12.5 KB smem), single wave of 2048 blocks.
// ---------------------------------------------------------------------------
__global__ void __launch_bounds__(32) pool_kernel(const float* __restrict__ x0,
                                                  const float* __restrict__ x1) {
    __shared__ float sm[2][1568];
    const int lane = threadIdx.x;
    const int ch = blockIdx.x;             // 0..2047
    const int b = ch >> 10;
    const int c = ch & 1023;

    const float* src = (c < C0)
        ? x0 + (size_t)(b * C0 + c) * TT * HW
        : x1 + (size_t)(b * C0 + (c - C0)) * TT * HW;

    uint32_t sb[2];
    sb[0] = (uint32_t)__cvta_generic_to_shared(&sm[0][0]);
    sb[1] = (uint32_t)__cvta_generic_to_shared(&sm[1][0]);

    auto issue = [&](int k, int buf) {
        const float4* g = (const float4*)(src + (size_t)k * 1568);
        uint32_t s = sb[buf];
#pragma unroll
        for (int i = 0; i < 12; i++)
            cpasync16(s + (i * 32 + lane) * 16, g + i * 32 + lane);
        if (lane < 8)
            cpasync16(s + (384 + lane) * 16, g + 384 + lane);
        cp_commit();
    };

    issue(0, 0);
    issue(1, 1);

    float* dst = &g_feats[(size_t)ch * TT];

    for (int k = 0; k < 32; k++) {
        if (k < 31) cp_wait<1>(); else cp_wait<0>();
        __syncwarp();
        const float* row = &sm[k & 1][lane * 49];
        float s = 0.f;
#pragma unroll
        for (int j = 0; j < 49; j++) s += row[j];
        dst[k * 32 + lane] = s * (1.0f / 49.0f);
        __syncwarp();
        if (k + 2 < 32) issue(k + 2, k & 1);
    }
}

// ---------------------------------------------------------------------------
// K2: projection GEMM with TF32 mma.sync (m16n8k8).
// Block: M=32 x N=128 x K=128, 256 threads.  KSPLIT=8 -> grid (64,8)=512.
// ---------------------------------------------------------------------------
__global__ void __launch_bounds__(256) gemm_proj_kernel(const float* __restrict__ proj_w) {
    __shared__ uint32_t As[32 * 40];       // [k][m] tf32
    __shared__ uint32_t Bs[32 * 136];      // [k][n] tf32
    const int tid = threadIdx.x;
    const int gm0 = blockIdx.x * 32;       // global row base (b*T + t)
    const int b = gm0 >> 10;
    const int t04 = (gm0 & 1023) >> 2;
    const int k0base = blockIdx.y * 128;

    const int w = tid >> 5;
    const int lane = tid & 31;
    const int m0 = (w & 1) * 16;
    const int n0 = (w >> 1) * 32;
    const int gid = lane >> 2;             // 0..7
    const int tig = lane & 3;              // 0..3

    float c[4][4];
#pragma unroll
    for (int i = 0; i < 4; i++)
#pragma unroll
        for (int j = 0; j < 4; j++) c[i][j] = 0.f;

    const float4* p4 = (const float4*)proj_w;
    const float4* f4 = (const float4*)g_feats;

    for (int kt = 0; kt < 128; kt += 32) {
        const int k0 = k0base + kt;
        {
            int kk = tid >> 3, m4 = tid & 7;
            float4 v = f4[((b << 10) + k0 + kk) * 256 + t04 + m4];
            uint32_t* dst = &As[kk * 40 + m4 * 4];
            dst[0] = f2tf32(v.x); dst[1] = f2tf32(v.y);
            dst[2] = f2tf32(v.z); dst[3] = f2tf32(v.w);
        }
#pragma unroll
        for (int r = 0; r < 4; r++) {
            int idx = tid + r * 256;
            int kk = idx >> 5, n4 = idx & 31;
            float4 v = p4[(k0 + kk) * 32 + n4];
            uint32_t* dst = &Bs[kk * 136 + n4 * 4];
            dst[0] = f2tf32(v.x); dst[1] = f2tf32(v.y);
            dst[2] = f2tf32(v.z); dst[3] = f2tf32(v.w);
        }
        __syncthreads();
#pragma unroll
        for (int k8 = 0; k8 < 32; k8 += 8) {
            uint32_t a0 = As[(k8 + tig) * 40 + m0 + gid];
            uint32_t a1 = As[(k8 + tig) * 40 + m0 + gid + 8];
            uint32_t a2 = As[(k8 + tig + 4) * 40 + m0 + gid];
            uint32_t a3 = As[(k8 + tig + 4) * 40 + m0 + gid + 8];
#pragma unroll
            for (int nf = 0; nf < 4; nf++) {
                int n = n0 + nf * 8 + gid;
                uint32_t b0 = Bs[(k8 + tig) * 136 + n];
                uint32_t b1 = Bs[(k8 + tig + 4) * 136 + n];
                mma_tf32(c[nf], a0, a1, a2, a3, b0, b1);
            }
        }
        __syncthreads();
    }
    float* dst = g_xpart[blockIdx.y];
#pragma unroll
    for (int nf = 0; nf < 4; nf++) {
        int col = n0 + nf * 8 + tig * 2;
        *(float2*)&dst[(gm0 + m0 + gid) * DD + col]     = make_float2(c[nf][0], c[nf][1]);
        *(float2*)&dst[(gm0 + m0 + gid + 8) * DD + col] = make_float2(c[nf][2], c[nf][3]);
    }
}

// ---------------------------------------------------------------------------
// K3: sum KSPLIT partials, L2-normalize each 128-dim row. Warp per row.
// ---------------------------------------------------------------------------
__global__ void __launch_bounds__(128) norm_kernel() {
    const int row = blockIdx.x * 4 + (threadIdx.x >> 5);   // 0..2047
    const int lane = threadIdx.x & 31;
    float4 v = make_float4(0.f, 0.f, 0.f, 0.f);
#pragma unroll
    for (int s = 0; s < KSPLIT; s++) {
        float4 p = ((const float4*)g_xpart[s])[row * 32 + lane];
        v.x += p.x; v.y += p.y; v.z += p.z; v.w += p.w;
    }
    float sq = v.x * v.x + v.y * v.y + v.z * v.z + v.w * v.w;
#pragma unroll
    for (int o = 16; o; o >>= 1) sq += __shfl_xor_sync(0xFFFFFFFFu, sq, o);
    const float inv = 1.0f / fmaxf(sqrtf(sq), 1e-12f);
    ((float4*)g_xnorm)[row * 32 + lane] =
        make_float4(v.x * inv, v.y * inv, v.z * inv, v.w * inv);
}

// ---------------------------------------------------------------------------
// K4: fused banded similarity (TF32 MMA) + fc + bias + relu — 512 threads.
// grid 128: block = 16 t rows, 16 warps (one n-tile of 8 s-cols per warp).
// Stage s-window of 128 rows (t0-50..t0+77, zeros outside [0,T)) in two
// 64-dim k-passes; MMA m16 x n128 x k128; scatter C into smem band tile at
// j = n - tl; fc in fp32 fma2 (lower 8 warps), fc_w staged by all 16 warps
// into the retired B region.
// ---------------------------------------------------------------------------
__global__ void __launch_bounds__(512) bandfc_kernel(const float* __restrict__ fc_w,
                                                     const float* __restrict__ fc_b,
                                                     float* __restrict__ out) {
    __shared__ uint32_t Asm[16 * 68];      // 16 t-rows x 64 dims (tf32, pad 4)
    __shared__ uint32_t Bsm[128 * 68];     // 128 s-rows x 64 dims; reused for fc_w
    __shared__ float band_sm[16 * 104];    // [tl][j] banded sims (j 0..100)

    const int tid = threadIdx.x;
    const int gt0 = blockIdx.x * 16;
    const int b = gt0 >> 10;
    const int t0 = gt0 & 1023;
    const int sbase = t0 - W2;             // global s of B row 0

    const int w = tid >> 5;                // warp 0..15 -> n-tile (8 s-cols)
    const int lane = tid & 31;
    const int gid = lane >> 2;             // 0..7
    const int tig = lane & 3;              // 0..3

    float acc[4] = {0.f, 0.f, 0.f, 0.f};

    const float4* xn4 = (const float4*)g_xnorm;

    for (int p = 0; p < 2; p++) {
        __syncthreads();
        // stage A: 16 rows x 16 float4 (lower 256 threads)
        if (tid < 256) {
            int r = tid >> 4, q = tid & 15;
            float4 v = xn4[((b << 10) + t0 + r) * 32 + p * 16 + q];
            uint32_t* d = &Asm[r * 68 + q * 4];
            d[0] = f2tf32(v.x); d[1] = f2tf32(v.y);
            d[2] = f2tf32(v.z); d[3] = f2tf32(v.w);
        }
        // stage B: 128 rows x 16 float4 (four per thread), zeros outside [0,T)
#pragma unroll
        for (int i = 0; i < 4; i++) {
            int idx = tid + i * 512;
            int r = idx >> 4, q = idx & 15;
            int s = sbase + r;
            float4 v = make_float4(0.f, 0.f, 0.f, 0.f);
            if (s >= 0 && s < TT) v = xn4[((b << 10) + s) * 32 + p * 16 + q];
            uint32_t* d = &Bsm[r * 68 + q * 4];
            d[0] = f2tf32(v.x); d[1] = f2tf32(v.y);
            d[2] = f2tf32(v.z); d[3] = f2tf32(v.w);
        }
        __syncthreads();
#pragma unroll
        for (int k8 = 0; k8 < 64; k8 += 8) {
            uint32_t a0 = Asm[gid * 68 + k8 + tig];
            uint32_t a1 = Asm[(gid + 8) * 68 + k8 + tig];
            uint32_t a2 = Asm[gid * 68 + k8 + tig + 4];
            uint32_t a3 = Asm[(gid + 8) * 68 + k8 + tig + 4];
            int nrow = w * 8 + gid;
            uint32_t b0 = Bsm[nrow * 68 + k8 + tig];
            uint32_t b1 = Bsm[nrow * 68 + k8 + tig + 4];
            mma_tf32(acc, a0, a1, a2, a3, b0, b1);
        }
    }

    // scatter C into the smem band tile: j = n - tl
    {
        int scol = w * 8 + tig * 2;
#pragma unroll
        for (int h = 0; h < 2; h++) {
            int tl = gid + h * 8;
            int j0 = scol - tl;
            if (j0 >= 0 && j0 <= 100) band_sm[tl * 104 + j0] = acc[h * 2 + 0];
            if (j0 + 1 >= 0 && j0 + 1 <= 100) band_sm[tl * 104 + j0 + 1] = acc[h * 2 + 1];
        }
    }

    // fc: out = relu(band @ fc_w + fc_b); fcw staged by all, computed by lower 256
    const int tl = tid >> 4;               // (tid<256) 0..15
    const int dg = tid & 15;
    float4* fcw = (float4*)Bsm;            // [101][17] float4, 27.5 KB

    for (int h = 0; h < 2; h++) {
        __syncthreads();                   // scatter done (h=0) / reads done (h=1)
#pragma unroll
        for (int i = 0; i < 4; i++) {
            int idx = tid + i * 512;
            if (idx < LL * 16) {
                int k = idx >> 4, q = idx & 15;
                fcw[k * 17 + q] = ((const float4*)fc_w)[k * 32 + h * 16 + q];
            }
        }
        __syncthreads();

        if (tid < 256) {
            unsigned long long acc0 = 0ull, acc1 = 0ull;
            const float* arow = &band_sm[tl * 104];
#pragma unroll 4
            for (int k = 0; k < LL; k++) {
                unsigned long long ap = pack2(arow[k], arow[k]);
                ulonglong2 b2 = *(const ulonglong2*)&fcw[k * 17 + dg];
                fma2(acc0, ap, b2.x);
                fma2(acc1, ap, b2.y);
            }
            float2 r0 = unpack2(acc0);
            float2 r1 = unpack2(acc1);
            float4 bias = ((const float4*)fc_b)[h * 16 + dg];
            float4 o;
            o.x = fmaxf(r0.x + bias.x, 0.f);
            o.y = fmaxf(r0.y + bias.y, 0.f);
            o.z = fmaxf(r1.x + bias.z, 0.f);
            o.w = fmaxf(r1.y + bias.w, 0.f);
            ((float4*)out)[(gt0 + tl) * 32 + h * 16 + dg] = o;
        }
    }
}

// ---------------------------------------------------------------------------
extern "C" void kernel_launch(void* const* d_in, const int* in_sizes, int n_in,
                              void* d_out, int out_size) {
    const float* x0     = (const float*)d_in[0];
    const float* x1     = (const float*)d_in[1];
    const float* proj_w = (const float*)d_in[2];
    const float* fc_w   = (const float*)d_in[3];
    const float* fc_b   = (const float*)d_in[4];
    float* out = (float*)d_out;

    pool_kernel<<<2048, 32>>>(x0, x1);
    gemm_proj_kernel<<<dim3(64, KSPLIT), 256>>>(proj_w);
    norm_kernel<<<512, 128>>>();
    bandfc_kernel<<<128, 512>>>(fc_w, fc_b, out);
}

// round 12
// speedup vs baseline: 1.3631x; 1.0010x over previous
#include <cuda_runtime.h>
#include <cstdint>

// Problem constants
#define BB 2
#define C0 512
#define CT 1024        // total channels
#define TT 1024        // time
#define HW 49          // 7*7
#define DD 128         // SIM_DIM / OUT_DIM
#define LL 101         // LOOKUP
#define W2 50

#define KSPLIT 8

// Scratch (device globals: allowed; no runtime allocation)
__device__ float g_feats[BB * CT * TT];               // [b][c][t]  8 MB
__device__ float g_xpart[KSPLIT][BB * TT * DD];       // k-split partials
__device__ float g_xnorm[BB * TT * DD];               // normalized rows, 1 MB

// ---- packed fp32x2 helpers (Blackwell) ------------------------------------
__device__ __forceinline__ void fma2(unsigned long long& acc,
                                     unsigned long long a, unsigned long long b) {
    asm("fma.rn.f32x2 %0, %1, %2, %0;" : "+l"(acc) : "l"(a), "l"(b));
}
__device__ __forceinline__ unsigned long long pack2(float x, float y) {
    unsigned long long r;
    asm("mov.b64 %0, {%1, %2};" : "=l"(r) : "f"(x), "f"(y));
    return r;
}
__device__ __forceinline__ float2 unpack2(unsigned long long v) {
    float2 f;
    asm("mov.b64 {%0, %1}, %2;" : "=f"(f.x), "=f"(f.y) : "l"(v));
    return f;
}
__device__ __forceinline__ uint32_t f2tf32(float x) {
    uint32_t r;
    asm("cvt.rna.tf32.f32 %0, %1;" : "=r"(r) : "f"(x));
    return r;
}
__device__ __forceinline__ void mma_tf32(float c[4], uint32_t a0, uint32_t a1,
                                         uint32_t a2, uint32_t a3,
                                         uint32_t b0, uint32_t b1) {
    asm("mma.sync.aligned.m16n8k8.row.col.f32.tf32.tf32.f32 "
        "{%0,%1,%2,%3}, {%4,%5,%6,%7}, {%8,%9}, {%0,%1,%2,%3};"
        : "+f"(c[0]), "+f"(c[1]), "+f"(c[2]), "+f"(c[3])
        : "r"(a0), "r"(a1), "r"(a2), "r"(a3), "r"(b0), "r"(b1));
}

// ---- cp.async helpers ------------------------------------------------------
__device__ __forceinline__ void cpasync16(uint32_t s, const void* g) {
    asm volatile("cp.async.cg.shared.global [%0], [%1], 16;" :: "r"(s), "l"(g));
}
__device__ __forceinline__ void cp_commit() {
    asm volatile("cp.async.commit_group;");
}
template <int N> __device__ __forceinline__ void cp_wait() {
    asm volatile("cp.async.wait_group %0;" :: "n"(N));
}

// ---------------------------------------------------------------------------
// K1: spatial mean pool — channel-streaming warps + cp.async double buffering.
// One warp per block (12.5 KB smem), single wave of 2048 blocks.
// ---------------------------------------------------------------------------
__global__ void __launch_bounds__(32) pool_kernel(const float* __restrict__ x0,
                                                  const float* __restrict__ x1) {
    __shared__ float sm[2][1568];
    const int lane = threadIdx.x;
    const int ch = blockIdx.x;             // 0..2047
    const int b = ch >> 10;
    const int c = ch & 1023;

    const float* src = (c < C0)
        ? x0 + (size_t)(b * C0 + c) * TT * HW
        : x1 + (size_t)(b * C0 + (c - C0)) * TT * HW;

    uint32_t sb[2];
    sb[0] = (uint32_t)__cvta_generic_to_shared(&sm[0][0]);
    sb[1] = (uint32_t)__cvta_generic_to_shared(&sm[1][0]);

    auto issue = [&](int k, int buf) {
        const float4* g = (const float4*)(src + (size_t)k * 1568);
        uint32_t s = sb[buf];
#pragma unroll
        for (int i = 0; i < 12; i++)
            cpasync16(s + (i * 32 + lane) * 16, g + i * 32 + lane);
        if (lane < 8)
            cpasync16(s + (384 + lane) * 16, g + 384 + lane);
        cp_commit();
    };

    issue(0, 0);
    issue(1, 1);

    float* dst = &g_feats[(size_t)ch * TT];

    for (int k = 0; k < 32; k++) {
        if (k < 31) cp_wait<1>(); else cp_wait<0>();
        __syncwarp();
        const float* row = &sm[k & 1][lane * 49];
        float s = 0.f;
#pragma unroll
        for (int j = 0; j < 49; j++) s += row[j];
        dst[k * 32 + lane] = s * (1.0f / 49.0f);
        __syncwarp();
        if (k + 2 < 32) issue(k + 2, k & 1);
    }
}

// ---------------------------------------------------------------------------
// K2: projection GEMM with TF32 mma.sync (m16n8k8).
// Block: M=32 x N=128 x K=128, 256 threads.  KSPLIT=8 -> grid (64,8)=512.
// ---------------------------------------------------------------------------
__global__ void __launch_bounds__(256) gemm_proj_kernel(const float* __restrict__ proj_w) {
    __shared__ uint32_t As[32 * 40];       // [k][m] tf32
    __shared__ uint32_t Bs[32 * 136];      // [k][n] tf32
    const int tid = threadIdx.x;
    const int gm0 = blockIdx.x * 32;       // global row base (b*T + t)
    const int b = gm0 >> 10;
    const int t04 = (gm0 & 1023) >> 2;
    const int k0base = blockIdx.y * 128;

    const int w = tid >> 5;
    const int lane = tid & 31;
    const int m0 = (w & 1) * 16;
    const int n0 = (w >> 1) * 32;
    const int gid = lane >> 2;             // 0..7
    const int tig = lane & 3;              // 0..3

    float c[4][4];
#pragma unroll
    for (int i = 0; i < 4; i++)
#pragma unroll
        for (int j = 0; j < 4; j++) c[i][j] = 0.f;

    const float4* p4 = (const float4*)proj_w;
    const float4* f4 = (const float4*)g_feats;

    for (int kt = 0; kt < 128; kt += 32) {
        const int k0 = k0base + kt;
        {
            int kk = tid >> 3, m4 = tid & 7;
            float4 v = f4[((b << 10) + k0 + kk) * 256 + t04 + m4];
            uint32_t* dst = &As[kk * 40 + m4 * 4];
            dst[0] = f2tf32(v.x); dst[1] = f2tf32(v.y);
            dst[2] = f2tf32(v.z); dst[3] = f2tf32(v.w);
        }
#pragma unroll
        for (int r = 0; r < 4; r++) {
            int idx = tid + r * 256;
            int kk = idx >> 5, n4 = idx & 31;
            float4 v = p4[(k0 + kk) * 32 + n4];
            uint32_t* dst = &Bs[kk * 136 + n4 * 4];
            dst[0] = f2tf32(v.x); dst[1] = f2tf32(v.y);
            dst[2] = f2tf32(v.z); dst[3] = f2tf32(v.w);
        }
        __syncthreads();
#pragma unroll
        for (int k8 = 0; k8 < 32; k8 += 8) {
            uint32_t a0 = As[(k8 + tig) * 40 + m0 + gid];
            uint32_t a1 = As[(k8 + tig) * 40 + m0 + gid + 8];
            uint32_t a2 = As[(k8 + tig + 4) * 40 + m0 + gid];
            uint32_t a3 = As[(k8 + tig + 4) * 40 + m0 + gid + 8];
#pragma unroll
            for (int nf = 0; nf < 4; nf++) {
                int n = n0 + nf * 8 + gid;
                uint32_t b0 = Bs[(k8 + tig) * 136 + n];
                uint32_t b1 = Bs[(k8 + tig + 4) * 136 + n];
                mma_tf32(c[nf], a0, a1, a2, a3, b0, b1);
            }
        }
        __syncthreads();
    }
    float* dst = g_xpart[blockIdx.y];
#pragma unroll
    for (int nf = 0; nf < 4; nf++) {
        int col = n0 + nf * 8 + tig * 2;
        *(float2*)&dst[(gm0 + m0 + gid) * DD + col]     = make_float2(c[nf][0], c[nf][1]);
        *(float2*)&dst[(gm0 + m0 + gid + 8) * DD + col] = make_float2(c[nf][2], c[nf][3]);
    }
}

// ---------------------------------------------------------------------------
// K3: sum KSPLIT partials, L2-normalize each 128-dim row. Warp per row.
// ---------------------------------------------------------------------------
__global__ void __launch_bounds__(128) norm_kernel() {
    const int row = blockIdx.x * 4 + (threadIdx.x >> 5);   // 0..2047
    const int lane = threadIdx.x & 31;
    float4 v = make_float4(0.f, 0.f, 0.f, 0.f);
#pragma unroll
    for (int s = 0; s < KSPLIT; s++) {
        float4 p = ((const float4*)g_xpart[s])[row * 32 + lane];
        v.x += p.x; v.y += p.y; v.z += p.z; v.w += p.w;
    }
    float sq = v.x * v.x + v.y * v.y + v.z * v.z + v.w * v.w;
#pragma unroll
    for (int o = 16; o; o >>= 1) sq += __shfl_xor_sync(0xFFFFFFFFu, sq, o);
    const float inv = 1.0f / fmaxf(sqrtf(sq), 1e-12f);
    ((float4*)g_xnorm)[row * 32 + lane] =
        make_float4(v.x * inv, v.y * inv, v.z * inv, v.w * inv);
}

// ---------------------------------------------------------------------------
// K4: fused banded similarity (TF32 MMA) + fc + bias + relu.  SINGLE k-pass,
// 2 barriers, ~133 KB dynamic smem.
// grid 128, 512 threads: block = 16 t rows.
//   phase 1: stage A (16x128), B (s-window 128 rows x 128 dims, zeros outside
//            [0,T)) and fc_w (101x128, own region) -> sync
//   phase 2: MMA m16 x n128 x k128 (warp = one 8-col n-tile, 16 chained mma),
//            scatter C from registers into band_sm at j = n - tl -> sync
//   phase 3: fc, warp = 8 t x 4 d-float4 (64B fcw per k-iter), fp32 fma2,
//            bias + relu, store.
// Smem layout (floats):  Bsm[128*132] | Asm[16*132] | fcw[101*33 f4] |
//                        band_sm[16*105]
// ---------------------------------------------------------------------------
#define BFC_SMEM_BYTES ((128 * 132 + 16 * 132 + 101 * 33 * 4 + 16 * 105) * 4)

__global__ void __launch_bounds__(512) bandfc_kernel(const float* __restrict__ fc_w,
                                                     const float* __restrict__ fc_b,
                                                     float* __restrict__ out) {
    extern __shared__ uint32_t dyn_sm[];
    uint32_t* Bsm = dyn_sm;                        // 128 x 132 tf32
    uint32_t* Asm = Bsm + 128 * 132;               // 16 x 132 tf32
    float4*   fcw = (float4*)(Asm + 16 * 132);     // 101 x 33 float4
    float*    band_sm = (float*)(fcw + 101 * 33);  // 16 x 105

    const int tid = threadIdx.x;
    const int gt0 = blockIdx.x * 16;
    const int b = gt0 >> 10;
    const int t0 = gt0 & 1023;
    const int sbase = t0 - W2;             // global s of B row 0

    const int w = tid >> 5;                // warp 0..15 -> n-tile (8 s-cols)
    const int lane = tid & 31;
    const int gid = lane >> 2;             // 0..7
    const int tig = lane & 3;              // 0..3

    const float4* xn4 = (const float4*)g_xnorm;

    // ---- phase 1: stage everything ----
    // A: 16 rows x 32 float4 -> one per thread
    {
        int r = tid >> 5, q = tid & 31;
        float4 v = xn4[((b << 10) + t0 + r) * 32 + q];
        uint32_t* d = &Asm[r * 132 + q * 4];
        d[0] = f2tf32(v.x); d[1] = f2tf32(v.y);
        d[2] = f2tf32(v.z); d[3] = f2tf32(v.w);
    }
    // B: 128 rows x 32 float4 -> eight per thread, zeros outside [0,T)
#pragma unroll
    for (int i = 0; i < 8; i++) {
        int idx = tid + i * 512;
        int r = idx >> 5, q = idx & 31;
        int s = sbase + r;
        float4 v = make_float4(0.f, 0.f, 0.f, 0.f);
        if (s >= 0 && s < TT) v = xn4[((b << 10) + s) * 32 + q];
        uint32_t* d = &Bsm[r * 132 + q * 4];
        d[0] = f2tf32(v.x); d[1] = f2tf32(v.y);
        d[2] = f2tf32(v.z); d[3] = f2tf32(v.w);
    }
    // fc_w: 101 rows x 32 float4 (fp32, kept exact)
#pragma unroll
    for (int i = 0; i < 7; i++) {
        int idx = tid + i * 512;
        if (idx < LL * 32) {
            int k = idx >> 5, q = idx & 31;
            fcw[k * 33 + q] = ((const float4*)fc_w)[k * 32 + q];
        }
    }
    __syncthreads();

    // ---- phase 2: MMA + scatter ----
    float acc[4] = {0.f, 0.f, 0.f, 0.f};
    const int nrow = w * 8 + gid;
#pragma unroll
    for (int k8 = 0; k8 < 128; k8 += 8) {
        uint32_t a0 = Asm[gid * 132 + k8 + tig];
        uint32_t a1 = Asm[(gid + 8) * 132 + k8 + tig];
        uint32_t a2 = Asm[gid * 132 + k8 + tig + 4];
        uint32_t a3 = Asm[(gid + 8) * 132 + k8 + tig + 4];
        uint32_t b0 = Bsm[nrow * 132 + k8 + tig];
        uint32_t b1 = Bsm[nrow * 132 + k8 + tig + 4];
        mma_tf32(acc, a0, a1, a2, a3, b0, b1);
    }
    // scatter: C[tl][n] -> band_sm[tl][n - tl]
    {
        int scol = w * 8 + tig * 2;
#pragma unroll
        for (int h = 0; h < 2; h++) {
            int tl = gid + h * 8;
            int j0 = scol - tl;
            if (j0 >= 0 && j0 <= 100) band_sm[tl * 105 + j0] = acc[h * 2 + 0];
            if (j0 + 1 >= 0 && j0 + 1 <= 100) band_sm[tl * 105 + j0 + 1] = acc[h * 2 + 1];
        }
    }
    __syncthreads();

    // ---- phase 3: fc (fp32) ----
    // warp = 8 t-rows x 4 d-float4:  w = tlg*8 + dgg  (tlg 0..1, dgg 0..7)
    const int tlg = w >> 3;
    const int dgg = w & 7;
    const int tl = tlg * 8 + (lane >> 2);  // 0..15
    const int dg = dgg * 4 + (lane & 3);   // 0..31

    unsigned long long acc0 = 0ull, acc1 = 0ull;
    const float* arow = &band_sm[tl * 105];
#pragma unroll 4
    for (int k = 0; k < LL; k++) {
        unsigned long long ap = pack2(arow[k], arow[k]);
        ulonglong2 b2 = *(const ulonglong2*)&fcw[k * 33 + dg];
        fma2(acc0, ap, b2.x);
        fma2(acc1, ap, b2.y);
    }
    float2 r0 = unpack2(acc0);
    float2 r1 = unpack2(acc1);
    float4 bias = ((const float4*)fc_b)[dg];
    float4 o;
    o.x = fmaxf(r0.x + bias.x, 0.f);
    o.y = fmaxf(r0.y + bias.y, 0.f);
    o.z = fmaxf(r1.x + bias.z, 0.f);
    o.w = fmaxf(r1.y + bias.w, 0.f);
    ((float4*)out)[(gt0 + tl) * 32 + dg] = o;
}

// ---------------------------------------------------------------------------
extern "C" void kernel_launch(void* const* d_in, const int* in_sizes, int n_in,
                              void* d_out, int out_size) {
    const float* x0     = (const float*)d_in[0];
    const float* x1     = (const float*)d_in[1];
    const float* proj_w = (const float*)d_in[2];
    const float* fc_w   = (const float*)d_in[3];
    const float* fc_b   = (const float*)d_in[4];
    float* out = (float*)d_out;

    cudaFuncSetAttribute(bandfc_kernel,
                         cudaFuncAttributeMaxDynamicSharedMemorySize,
                         BFC_SMEM_BYTES);

    pool_kernel<<<2048, 32>>>(x0, x1);
    gemm_proj_kernel<<<dim3(64, KSPLIT), 256>>>(proj_w);
    norm_kernel<<<512, 128>>>();
    bandfc_kernel<<<128, 512, BFC_SMEM_BYTES>>>(fc_w, fc_b, out);
}

// round 13
// speedup vs baseline: 1.4225x; 1.0436x over previous
#include <cuda_runtime.h>
#include <cstdint>

// Problem constants
#define BB 2
#define C0 512
#define CT 1024        // total channels
#define TT 1024        // time
#define HW 49          // 7*7
#define DD 128         // SIM_DIM / OUT_DIM
#define LL 101         // LOOKUP
#define W2 50

#define KSPLIT 8

// Scratch (device globals: allowed; no runtime allocation)
__device__ float g_feats[BB * CT * TT];               // [b][c][t]  8 MB
__device__ float g_xpart[KSPLIT][BB * TT * DD];       // k-split partials
__device__ float g_xnorm[BB * TT * DD];               // normalized rows, 1 MB

// ---- packed fp32x2 helpers (Blackwell) ------------------------------------
__device__ __forceinline__ void fma2(unsigned long long& acc,
                                     unsigned long long a, unsigned long long b) {
    asm("fma.rn.f32x2 %0, %1, %2, %0;" : "+l"(acc) : "l"(a), "l"(b));
}
__device__ __forceinline__ unsigned long long pack2(float x, float y) {
    unsigned long long r;
    asm("mov.b64 %0, {%1, %2};" : "=l"(r) : "f"(x), "f"(y));
    return r;
}
__device__ __forceinline__ float2 unpack2(unsigned long long v) {
    float2 f;
    asm("mov.b64 {%0, %1}, %2;" : "=f"(f.x), "=f"(f.y) : "l"(v));
    return f;
}
__device__ __forceinline__ uint32_t f2tf32(float x) {
    uint32_t r;
    asm("cvt.rna.tf32.f32 %0, %1;" : "=r"(r) : "f"(x));
    return r;
}
__device__ __forceinline__ void mma_tf32(float c[4], uint32_t a0, uint32_t a1,
                                         uint32_t a2, uint32_t a3,
                                         uint32_t b0, uint32_t b1) {
    asm("mma.sync.aligned.m16n8k8.row.col.f32.tf32.tf32.f32 "
        "{%0,%1,%2,%3}, {%4,%5,%6,%7}, {%8,%9}, {%0,%1,%2,%3};"
        : "+f"(c[0]), "+f"(c[1]), "+f"(c[2]), "+f"(c[3])
        : "r"(a0), "r"(a1), "r"(a2), "r"(a3), "r"(b0), "r"(b1));
}

// ---- cp.async helpers ------------------------------------------------------
__device__ __forceinline__ void cpasync16(uint32_t s, const void* g) {
    asm volatile("cp.async.cg.shared.global [%0], [%1], 16;" :: "r"(s), "l"(g));
}
__device__ __forceinline__ void cp_commit() {
    asm volatile("cp.async.commit_group;");
}
template <int N> __device__ __forceinline__ void cp_wait() {
    asm volatile("cp.async.wait_group %0;" :: "n"(N));
}

// ---------------------------------------------------------------------------
// K1: spatial mean pool — channel-streaming warps + cp.async double buffering.
// One warp per block (12.5 KB smem), single wave of 2048 blocks.
// ---------------------------------------------------------------------------
__global__ void __launch_bounds__(32) pool_kernel(const float* __restrict__ x0,
                                                  const float* __restrict__ x1) {
    __shared__ float sm[2][1568];
    const int lane = threadIdx.x;
    const int ch = blockIdx.x;             // 0..2047
    const int b = ch >> 10;
    const int c = ch & 1023;

    const float* src = (c < C0)
        ? x0 + (size_t)(b * C0 + c) * TT * HW
        : x1 + (size_t)(b * C0 + (c - C0)) * TT * HW;

    uint32_t sb[2];
    sb[0] = (uint32_t)__cvta_generic_to_shared(&sm[0][0]);
    sb[1] = (uint32_t)__cvta_generic_to_shared(&sm[1][0]);

    auto issue = [&](int k, int buf) {
        const float4* g = (const float4*)(src + (size_t)k * 1568);
        uint32_t s = sb[buf];
#pragma unroll
        for (int i = 0; i < 12; i++)
            cpasync16(s + (i * 32 + lane) * 16, g + i * 32 + lane);
        if (lane < 8)
            cpasync16(s + (384 + lane) * 16, g + 384 + lane);
        cp_commit();
    };

    issue(0, 0);
    issue(1, 1);

    float* dst = &g_feats[(size_t)ch * TT];

    for (int k = 0; k < 32; k++) {
        if (k < 31) cp_wait<1>(); else cp_wait<0>();
        __syncwarp();
        const float* row = &sm[k & 1][lane * 49];
        float s = 0.f;
#pragma unroll
        for (int j = 0; j < 49; j++) s += row[j];
        dst[k * 32 + lane] = s * (1.0f / 49.0f);
        __syncwarp();
        if (k + 2 < 32) issue(k + 2, k & 1);
    }
}

// ---------------------------------------------------------------------------
// K2: projection GEMM with TF32 mma.sync (m16n8k8).
// Block: M=32 x N=128 x K=128, 256 threads.  KSPLIT=8 -> grid (64,8)=512.
// ---------------------------------------------------------------------------
__global__ void __launch_bounds__(256) gemm_proj_kernel(const float* __restrict__ proj_w) {
    __shared__ uint32_t As[32 * 40];       // [k][m] tf32
    __shared__ uint32_t Bs[32 * 136];      // [k][n] tf32
    const int tid = threadIdx.x;
    const int gm0 = blockIdx.x * 32;       // global row base (b*T + t)
    const int b = gm0 >> 10;
    const int t04 = (gm0 & 1023) >> 2;
    const int k0base = blockIdx.y * 128;

    const int w = tid >> 5;
    const int lane = tid & 31;
    const int m0 = (w & 1) * 16;
    const int n0 = (w >> 1) * 32;
    const int gid = lane >> 2;             // 0..7
    const int tig = lane & 3;              // 0..3

    float c[4][4];
#pragma unroll
    for (int i = 0; i < 4; i++)
#pragma unroll
        for (int j = 0; j < 4; j++) c[i][j] = 0.f;

    const float4* p4 = (const float4*)proj_w;
    const float4* f4 = (const float4*)g_feats;

    for (int kt = 0; kt < 128; kt += 32) {
        const int k0 = k0base + kt;
        {
            int kk = tid >> 3, m4 = tid & 7;
            float4 v = f4[((b << 10) + k0 + kk) * 256 + t04 + m4];
            uint32_t* dst = &As[kk * 40 + m4 * 4];
            dst[0] = f2tf32(v.x); dst[1] = f2tf32(v.y);
            dst[2] = f2tf32(v.z); dst[3] = f2tf32(v.w);
        }
#pragma unroll
        for (int r = 0; r < 4; r++) {
            int idx = tid + r * 256;
            int kk = idx >> 5, n4 = idx & 31;
            float4 v = p4[(k0 + kk) * 32 + n4];
            uint32_t* dst = &Bs[kk * 136 + n4 * 4];
            dst[0] = f2tf32(v.x); dst[1] = f2tf32(v.y);
            dst[2] = f2tf32(v.z); dst[3] = f2tf32(v.w);
        }
        __syncthreads();
#pragma unroll
        for (int k8 = 0; k8 < 32; k8 += 8) {
            uint32_t a0 = As[(k8 + tig) * 40 + m0 + gid];
            uint32_t a1 = As[(k8 + tig) * 40 + m0 + gid + 8];
            uint32_t a2 = As[(k8 + tig + 4) * 40 + m0 + gid];
            uint32_t a3 = As[(k8 + tig + 4) * 40 + m0 + gid + 8];
#pragma unroll
            for (int nf = 0; nf < 4; nf++) {
                int n = n0 + nf * 8 + gid;
                uint32_t b0 = Bs[(k8 + tig) * 136 + n];
                uint32_t b1 = Bs[(k8 + tig + 4) * 136 + n];
                mma_tf32(c[nf], a0, a1, a2, a3, b0, b1);
            }
        }
        __syncthreads();
    }
    float* dst = g_xpart[blockIdx.y];
#pragma unroll
    for (int nf = 0; nf < 4; nf++) {
        int col = n0 + nf * 8 + tig * 2;
        *(float2*)&dst[(gm0 + m0 + gid) * DD + col]     = make_float2(c[nf][0], c[nf][1]);
        *(float2*)&dst[(gm0 + m0 + gid + 8) * DD + col] = make_float2(c[nf][2], c[nf][3]);
    }
}

// ---------------------------------------------------------------------------
// K3: sum KSPLIT partials, L2-normalize each 128-dim row. Warp per row.
// ---------------------------------------------------------------------------
__global__ void __launch_bounds__(128) norm_kernel() {
    const int row = blockIdx.x * 4 + (threadIdx.x >> 5);   // 0..2047
    const int lane = threadIdx.x & 31;
    float4 v = make_float4(0.f, 0.f, 0.f, 0.f);
#pragma unroll
    for (int s = 0; s < KSPLIT; s++) {
        float4 p = ((const float4*)g_xpart[s])[row * 32 + lane];
        v.x += p.x; v.y += p.y; v.z += p.z; v.w += p.w;
    }
    float sq = v.x * v.x + v.y * v.y + v.z * v.z + v.w * v.w;
#pragma unroll
    for (int o = 16; o; o >>= 1) sq += __shfl_xor_sync(0xFFFFFFFFu, sq, o);
    const float inv = 1.0f / fmaxf(sqrtf(sq), 1e-12f);
    ((float4*)g_xnorm)[row * 32 + lane] =
        make_float4(v.x * inv, v.y * inv, v.z * inv, v.w * inv);
}

// ---------------------------------------------------------------------------
// K4: fused banded similarity + fc, BOTH on TF32 tensor cores.  2 barriers.
// grid 128, 512 threads: block = 16 t rows.
//   phase 1: stage A (16x128 tf32), B (s-window 128x128 tf32, zeros outside
//            [0,T)), fc_w as tf32 [k 104][d 128] (rows 101-103 zero), zero
//            band k-pad cols -> sync
//   phase 2: sim MMA m16 x n128 x k128 (warp = 8-col n-tile, 16 chained mma),
//            scatter C (as tf32) into band_sm[tl][j], j = n - tl -> sync
//   phase 3: fc MMA m16 x n128 x k104 (warp = 8-col d-tile, 13 chained mma),
//            bias + relu from registers, store.
// Strides: A/band 132 (bank = gid*4+tig = lane), B_frag source 136
// (bank = tig*8+gid) -> all fragment LDS conflict-free.
// Smem: Bsm 128*132 | Asm 16*132 | fcw 104*136 | band 16*132 = 141 KB.
// ---------------------------------------------------------------------------
#define BFC_SMEM_WORDS (128 * 132 + 16 * 132 + 104 * 136 + 16 * 132)
#define BFC_SMEM_BYTES (BFC_SMEM_WORDS * 4)

__global__ void __launch_bounds__(512) bandfc_kernel(const float* __restrict__ fc_w,
                                                     const float* __restrict__ fc_b,
                                                     float* __restrict__ out) {
    extern __shared__ uint32_t dyn_sm[];
    uint32_t* Bsm = dyn_sm;                        // 128 x 132 tf32
    uint32_t* Asm = Bsm + 128 * 132;               // 16 x 132 tf32
    uint32_t* fcw = Asm + 16 * 132;                // 104 x 136 tf32 [k][d]
    uint32_t* band_sm = fcw + 104 * 136;           // 16 x 132 tf32 [tl][j]

    const int tid = threadIdx.x;
    const int gt0 = blockIdx.x * 16;
    const int b = gt0 >> 10;
    const int t0 = gt0 & 1023;
    const int sbase = t0 - W2;             // global s of B row 0

    const int w = tid >> 5;                // warp 0..15
    const int lane = tid & 31;
    const int gid = lane >> 2;             // 0..7
    const int tig = lane & 3;              // 0..3

    const float4* xn4 = (const float4*)g_xnorm;

    // ---- phase 1: stage everything ----
    // A: 16 rows x 32 float4 -> one per thread
    {
        int r = tid >> 5, q = tid & 31;
        float4 v = xn4[((b << 10) + t0 + r) * 32 + q];
        uint32_t* d = &Asm[r * 132 + q * 4];
        d[0] = f2tf32(v.x); d[1] = f2tf32(v.y);
        d[2] = f2tf32(v.z); d[3] = f2tf32(v.w);
    }
    // B: 128 rows x 32 float4 -> eight per thread, zeros outside [0,T)
#pragma unroll
    for (int i = 0; i < 8; i++) {
        int idx = tid + i * 512;
        int r = idx >> 5, q = idx & 31;
        int s = sbase + r;
        float4 v = make_float4(0.f, 0.f, 0.f, 0.f);
        if (s >= 0 && s < TT) v = xn4[((b << 10) + s) * 32 + q];
        uint32_t* d = &Bsm[r * 132 + q * 4];
        d[0] = f2tf32(v.x); d[1] = f2tf32(v.y);
        d[2] = f2tf32(v.z); d[3] = f2tf32(v.w);
    }
    // fc_w -> tf32 [k][d], stride 136; 101 rows x 32 float4
#pragma unroll
    for (int i = 0; i < 7; i++) {
        int idx = tid + i * 512;
        if (idx < LL * 32) {
            int k = idx >> 5, q = idx & 31;
            float4 v = ((const float4*)fc_w)[k * 32 + q];
            uint32_t* d = &fcw[k * 136 + q * 4];
            d[0] = f2tf32(v.x); d[1] = f2tf32(v.y);
            d[2] = f2tf32(v.z); d[3] = f2tf32(v.w);
        }
    }
    // zero fc_w k-pad rows 101..103 (3 x 128 d)
    if (tid < 384) {
        int k = LL + tid / DD, d = tid % DD;
        fcw[k * 136 + d] = 0u;
    }
    // zero band k-pad cols 101..103 (16 x 3)
    if (tid < 48) {
        int tl = tid / 3, kk = LL + tid % 3;
        band_sm[tl * 132 + kk] = 0u;
    }
    __syncthreads();

    // ---- phase 2: sim MMA + scatter (as tf32) ----
    {
        float acc[4] = {0.f, 0.f, 0.f, 0.f};
        const int nrow = w * 8 + gid;
#pragma unroll
        for (int k8 = 0; k8 < 128; k8 += 8) {
            uint32_t a0 = Asm[gid * 132 + k8 + tig];
            uint32_t a1 = Asm[(gid + 8) * 132 + k8 + tig];
            uint32_t a2 = Asm[gid * 132 + k8 + tig + 4];
            uint32_t a3 = Asm[(gid + 8) * 132 + k8 + tig + 4];
            uint32_t b0 = Bsm[nrow * 132 + k8 + tig];
            uint32_t b1 = Bsm[nrow * 132 + k8 + tig + 4];
            mma_tf32(acc, a0, a1, a2, a3, b0, b1);
        }
        int scol = w * 8 + tig * 2;
#pragma unroll
        for (int h = 0; h < 2; h++) {
            int tl = gid + h * 8;
            int j0 = scol - tl;
            if (j0 >= 0 && j0 <= 100) band_sm[tl * 132 + j0] = f2tf32(acc[h * 2 + 0]);
            if (j0 + 1 >= 0 && j0 + 1 <= 100) band_sm[tl * 132 + j0 + 1] = f2tf32(acc[h * 2 + 1]);
        }
    }
    __syncthreads();

    // ---- phase 3: fc MMA (m16 x n128 x k104) + bias + relu ----
    {
        float c[4] = {0.f, 0.f, 0.f, 0.f};
        const int n0 = w * 8;
#pragma unroll
        for (int k8 = 0; k8 < 104; k8 += 8) {
            uint32_t a0 = band_sm[gid * 132 + k8 + tig];
            uint32_t a1 = band_sm[(gid + 8) * 132 + k8 + tig];
            uint32_t a2 = band_sm[gid * 132 + k8 + tig + 4];
            uint32_t a3 = band_sm[(gid + 8) * 132 + k8 + tig + 4];
            uint32_t b0 = fcw[(k8 + tig) * 136 + n0 + gid];
            uint32_t b1 = fcw[(k8 + tig + 4) * 136 + n0 + gid];
            mma_tf32(c, a0, a1, a2, a3, b0, b1);
        }
        int d = n0 + tig * 2;
        float2 bias = *(const float2*)&fc_b[d];
        float2 o0, o1;
        o0.x = fmaxf(c[0] + bias.x, 0.f);
        o0.y = fmaxf(c[1] + bias.y, 0.f);
        o1.x = fmaxf(c[2] + bias.x, 0.f);
        o1.y = fmaxf(c[3] + bias.y, 0.f);
        *(float2*)&out[(gt0 + gid) * DD + d]     = o0;
        *(float2*)&out[(gt0 + gid + 8) * DD + d] = o1;
    }
}

// ---------------------------------------------------------------------------
extern "C" void kernel_launch(void* const* d_in, const int* in_sizes, int n_in,
                              void* d_out, int out_size) {
    const float* x0     = (const float*)d_in[0];
    const float* x1     = (const float*)d_in[1];
    const float* proj_w = (const float*)d_in[2];
    const float* fc_w   = (const float*)d_in[3];
    const float* fc_b   = (const float*)d_in[4];
    float* out = (float*)d_out;

    cudaFuncSetAttribute(bandfc_kernel,
                         cudaFuncAttributeMaxDynamicSharedMemorySize,
                         BFC_SMEM_BYTES);

    pool_kernel<<<2048, 32>>>(x0, x1);
    gemm_proj_kernel<<<dim3(64, KSPLIT), 256>>>(proj_w);
    norm_kernel<<<512, 128>>>();
    bandfc_kernel<<<128, 512, BFC_SMEM_BYTES>>>(fc_w, fc_b, out);
}

// round 14
// speedup vs baseline: 1.4251x; 1.0018x over previous
#include <cuda_runtime.h>
#include <cstdint>

// Problem constants
#define BB 2
#define C0 512
#define CT 1024        // total channels
#define TT 1024        // time
#define HW 49          // 7*7
#define DD 128         // SIM_DIM / OUT_DIM
#define LL 101         // LOOKUP
#define W2 50

#define KSPLIT 8

// Scratch (device globals: allowed; no runtime allocation)
__device__ float g_feats[BB * CT * TT];               // [b][c][t]  8 MB
__device__ float g_xpart[KSPLIT][BB * TT * DD];       // k-split partials
__device__ uint32_t g_xnorm[BB * TT * DD];            // normalized rows, tf32 bits
__device__ uint32_t g_fcw32[104 * 136];               // fc_w as tf32, prepadded

// ---- packed fp32x2 / tf32 helpers ------------------------------------------
__device__ __forceinline__ uint32_t f2tf32(float x) {
    uint32_t r;
    asm("cvt.rna.tf32.f32 %0, %1;" : "=r"(r) : "f"(x));
    return r;
}
__device__ __forceinline__ void mma_tf32(float c[4], uint32_t a0, uint32_t a1,
                                         uint32_t a2, uint32_t a3,
                                         uint32_t b0, uint32_t b1) {
    asm("mma.sync.aligned.m16n8k8.row.col.f32.tf32.tf32.f32 "
        "{%0,%1,%2,%3}, {%4,%5,%6,%7}, {%8,%9}, {%0,%1,%2,%3};"
        : "+f"(c[0]), "+f"(c[1]), "+f"(c[2]), "+f"(c[3])
        : "r"(a0), "r"(a1), "r"(a2), "r"(a3), "r"(b0), "r"(b1));
}

// ---- cp.async helpers ------------------------------------------------------
__device__ __forceinline__ void cpasync16(uint32_t s, const void* g) {
    asm volatile("cp.async.cg.shared.global [%0], [%1], 16;" :: "r"(s), "l"(g));
}
__device__ __forceinline__ void cp_commit() {
    asm volatile("cp.async.commit_group;");
}
template <int N> __device__ __forceinline__ void cp_wait() {
    asm volatile("cp.async.wait_group %0;" :: "n"(N));
}

// ---------------------------------------------------------------------------
// K1: spatial mean pool — channel-streaming warps + cp.async double buffering.
// One warp per block (12.5 KB smem), single wave of 2048 blocks.
// ---------------------------------------------------------------------------
__global__ void __launch_bounds__(32) pool_kernel(const float* __restrict__ x0,
                                                  const float* __restrict__ x1) {
    __shared__ float sm[2][1568];
    const int lane = threadIdx.x;
    const int ch = blockIdx.x;             // 0..2047
    const int b = ch >> 10;
    const int c = ch & 1023;

    const float* src = (c < C0)
        ? x0 + (size_t)(b * C0 + c) * TT * HW
        : x1 + (size_t)(b * C0 + (c - C0)) * TT * HW;

    uint32_t sb[2];
    sb[0] = (uint32_t)__cvta_generic_to_shared(&sm[0][0]);
    sb[1] = (uint32_t)__cvta_generic_to_shared(&sm[1][0]);

    auto issue = [&](int k, int buf) {
        const float4* g = (const float4*)(src + (size_t)k * 1568);
        uint32_t s = sb[buf];
#pragma unroll
        for (int i = 0; i < 12; i++)
            cpasync16(s + (i * 32 + lane) * 16, g + i * 32 + lane);
        if (lane < 8)
            cpasync16(s + (384 + lane) * 16, g + 384 + lane);
        cp_commit();
    };

    issue(0, 0);
    issue(1, 1);

    float* dst = &g_feats[(size_t)ch * TT];

    for (int k = 0; k < 32; k++) {
        if (k < 31) cp_wait<1>(); else cp_wait<0>();
        __syncwarp();
        const float* row = &sm[k & 1][lane * 49];
        float s = 0.f;
#pragma unroll
        for (int j = 0; j < 49; j++) s += row[j];
        dst[k * 32 + lane] = s * (1.0f / 49.0f);
        __syncwarp();
        if (k + 2 < 32) issue(k + 2, k & 1);
    }
}

// ---------------------------------------------------------------------------
// K2: projection GEMM with TF32 mma.sync (m16n8k8).
// Block: M=32 x N=128 x K=128, 256 threads.  KSPLIT=8 -> grid (64,8)=512.
// ---------------------------------------------------------------------------
__global__ void __launch_bounds__(256) gemm_proj_kernel(const float* __restrict__ proj_w) {
    __shared__ uint32_t As[32 * 40];       // [k][m] tf32
    __shared__ uint32_t Bs[32 * 136];      // [k][n] tf32
    const int tid = threadIdx.x;
    const int gm0 = blockIdx.x * 32;       // global row base (b*T + t)
    const int b = gm0 >> 10;
    const int t04 = (gm0 & 1023) >> 2;
    const int k0base = blockIdx.y * 128;

    const int w = tid >> 5;
    const int lane = tid & 31;
    const int m0 = (w & 1) * 16;
    const int n0 = (w >> 1) * 32;
    const int gid = lane >> 2;             // 0..7
    const int tig = lane & 3;              // 0..3

    float c[4][4];
#pragma unroll
    for (int i = 0; i < 4; i++)
#pragma unroll
        for (int j = 0; j < 4; j++) c[i][j] = 0.f;

    const float4* p4 = (const float4*)proj_w;
    const float4* f4 = (const float4*)g_feats;

    for (int kt = 0; kt < 128; kt += 32) {
        const int k0 = k0base + kt;
        {
            int kk = tid >> 3, m4 = tid & 7;
            float4 v = f4[((b << 10) + k0 + kk) * 256 + t04 + m4];
            uint32_t* dst = &As[kk * 40 + m4 * 4];
            dst[0] = f2tf32(v.x); dst[1] = f2tf32(v.y);
            dst[2] = f2tf32(v.z); dst[3] = f2tf32(v.w);
        }
#pragma unroll
        for (int r = 0; r < 4; r++) {
            int idx = tid + r * 256;
            int kk = idx >> 5, n4 = idx & 31;
            float4 v = p4[(k0 + kk) * 32 + n4];
            uint32_t* dst = &Bs[kk * 136 + n4 * 4];
            dst[0] = f2tf32(v.x); dst[1] = f2tf32(v.y);
            dst[2] = f2tf32(v.z); dst[3] = f2tf32(v.w);
        }
        __syncthreads();
#pragma unroll
        for (int k8 = 0; k8 < 32; k8 += 8) {
            uint32_t a0 = As[(k8 + tig) * 40 + m0 + gid];
            uint32_t a1 = As[(k8 + tig) * 40 + m0 + gid + 8];
            uint32_t a2 = As[(k8 + tig + 4) * 40 + m0 + gid];
            uint32_t a3 = As[(k8 + tig + 4) * 40 + m0 + gid + 8];
#pragma unroll
            for (int nf = 0; nf < 4; nf++) {
                int n = n0 + nf * 8 + gid;
                uint32_t b0 = Bs[(k8 + tig) * 136 + n];
                uint32_t b1 = Bs[(k8 + tig + 4) * 136 + n];
                mma_tf32(c[nf], a0, a1, a2, a3, b0, b1);
            }
        }
        __syncthreads();
    }
    float* dst = g_xpart[blockIdx.y];
#pragma unroll
    for (int nf = 0; nf < 4; nf++) {
        int col = n0 + nf * 8 + tig * 2;
        *(float2*)&dst[(gm0 + m0 + gid) * DD + col]     = make_float2(c[nf][0], c[nf][1]);
        *(float2*)&dst[(gm0 + m0 + gid + 8) * DD + col] = make_float2(c[nf][2], c[nf][3]);
    }
}

// ---------------------------------------------------------------------------
// K3: sum KSPLIT partials, L2-normalize, store as TF32 bits.  Warp per row.
// Also converts fc_w into prepadded tf32 g_fcw32 (spare thread capacity).
// ---------------------------------------------------------------------------
__global__ void __launch_bounds__(128) norm_kernel(const float* __restrict__ fc_w) {
    // fc_w -> g_fcw32 [k 104][d 136], rows >= 101 and cols >= 128 zero
    {
        int gidx = blockIdx.x * 128 + threadIdx.x;     // 65536 threads >= 14144
        if (gidx < 104 * 136) {
            int k = gidx / 136, d = gidx - k * 136;
            uint32_t v = 0u;
            if (k < LL && d < DD) v = f2tf32(fc_w[k * DD + d]);
            g_fcw32[gidx] = v;
        }
    }

    const int row = blockIdx.x * 4 + (threadIdx.x >> 5);   // 0..2047
    const int lane = threadIdx.x & 31;
    float4 v = make_float4(0.f, 0.f, 0.f, 0.f);
#pragma unroll
    for (int s = 0; s < KSPLIT; s++) {
        float4 p = ((const float4*)g_xpart[s])[row * 32 + lane];
        v.x += p.x; v.y += p.y; v.z += p.z; v.w += p.w;
    }
    float sq = v.x * v.x + v.y * v.y + v.z * v.z + v.w * v.w;
#pragma unroll
    for (int o = 16; o; o >>= 1) sq += __shfl_xor_sync(0xFFFFFFFFu, sq, o);
    const float inv = 1.0f / fmaxf(sqrtf(sq), 1e-12f);
    uint4 o;
    o.x = f2tf32(v.x * inv); o.y = f2tf32(v.y * inv);
    o.z = f2tf32(v.z * inv); o.w = f2tf32(v.w * inv);
    ((uint4*)g_xnorm)[row * 32 + lane] = o;
}

// ---------------------------------------------------------------------------
// K4: fused banded similarity + fc, BOTH on TF32 tensor cores.
// Staging is pure cp.async (xnorm and fcw are pre-converted tf32 in gmem);
// the A tile is the middle of the B window (rows 50..65) -> no separate Asm.
// grid 128, 512 threads: block = 16 t rows.
//   phase 1: cp.async B window (128 rows x 128 dims; STS zeros for rows
//            outside [0,T)) + cp.async fcw (linear) + zero band k-pad -> sync
//   phase 2: sim MMA m16 x n128 x k128, scatter C (tf32) into band_sm -> sync
//   phase 3: fc MMA m16 x n128 x k104, bias + relu, store.
// Smem: Bsm 128*132 | fcw 104*136 | band 16*132 = 129.5 KB.
// ---------------------------------------------------------------------------
#define BFC_SMEM_WORDS (128 * 132 + 104 * 136 + 16 * 132)
#define BFC_SMEM_BYTES (BFC_SMEM_WORDS * 4)

__global__ void __launch_bounds__(512) bandfc_kernel(const float* __restrict__ fc_b,
                                                     float* __restrict__ out) {
    extern __shared__ uint32_t dyn_sm[];
    uint32_t* Bsm = dyn_sm;                        // 128 x 132 tf32
    uint32_t* fcw = Bsm + 128 * 132;               // 104 x 136 tf32 [k][d]
    uint32_t* band_sm = fcw + 104 * 136;           // 16 x 132 tf32 [tl][j]
    uint32_t* Asm = Bsm + W2 * 132;                // A rows = B rows 50..65

    const int tid = threadIdx.x;
    const int gt0 = blockIdx.x * 16;
    const int b = gt0 >> 10;
    const int t0 = gt0 & 1023;
    const int sbase = t0 - W2;             // global s of B row 0

    const int w = tid >> 5;                // warp 0..15
    const int lane = tid & 31;
    const int gid = lane >> 2;             // 0..7
    const int tig = lane & 3;              // 0..3

    const uint32_t sm_base = (uint32_t)__cvta_generic_to_shared(dyn_sm);

    // ---- phase 1: stage via cp.async ----
    // B window: 128 rows x 32 chunks (16B) = 4096 chunks, 8 per thread
#pragma unroll
    for (int i = 0; i < 8; i++) {
        int idx = tid + i * 512;
        int r = idx >> 5, q = idx & 31;    // q = 16B chunk within row
        int s = sbase + r;
        uint32_t dst_off = (r * 132 + q * 4) * 4;
        if (s >= 0 && s < TT) {
            cpasync16(sm_base + dst_off, &g_xnorm[(((b << 10) + s) << 7) + q * 4]);
        } else {
            *(float4*)((char*)dyn_sm + dst_off) = make_float4(0.f, 0.f, 0.f, 0.f);
        }
    }
    // fcw: linear copy of 104*136 words = 3536 chunks
    {
        const uint32_t fcw_off = 128 * 132 * 4;
        for (int i = tid; i < 3536; i += 512)
            cpasync16(sm_base + fcw_off + i * 16, &g_fcw32[i * 4]);
    }
    cp_commit();
    // band k-pad cols 101..103 (16 x 3)
    if (tid < 48) {
        int tl = tid / 3, kk = LL + tid % 3;
        band_sm[tl * 132 + kk] = 0u;
    }
    cp_wait<0>();
    __syncthreads();

    // ---- phase 2: sim MMA + scatter (as tf32) ----
    {
        float acc[4] = {0.f, 0.f, 0.f, 0.f};
        const int nrow = w * 8 + gid;
#pragma unroll
        for (int k8 = 0; k8 < 128; k8 += 8) {
            uint32_t a0 = Asm[gid * 132 + k8 + tig];
            uint32_t a1 = Asm[(gid + 8) * 132 + k8 + tig];
            uint32_t a2 = Asm[gid * 132 + k8 + tig + 4];
            uint32_t a3 = Asm[(gid + 8) * 132 + k8 + tig + 4];
            uint32_t b0 = Bsm[nrow * 132 + k8 + tig];
            uint32_t b1 = Bsm[nrow * 132 + k8 + tig + 4];
            mma_tf32(acc, a0, a1, a2, a3, b0, b1);
        }
        int scol = w * 8 + tig * 2;
#pragma unroll
        for (int h = 0; h < 2; h++) {
            int tl = gid + h * 8;
            int j0 = scol - tl;
            if (j0 >= 0 && j0 <= 100) band_sm[tl * 132 + j0] = f2tf32(acc[h * 2 + 0]);
            if (j0 + 1 >= 0 && j0 + 1 <= 100) band_sm[tl * 132 + j0 + 1] = f2tf32(acc[h * 2 + 1]);
        }
    }
    __syncthreads();

    // ---- phase 3: fc MMA (m16 x n128 x k104) + bias + relu ----
    {
        float c[4] = {0.f, 0.f, 0.f, 0.f};
        const int n0 = w * 8;
#pragma unroll
        for (int k8 = 0; k8 < 104; k8 += 8) {
            uint32_t a0 = band_sm[gid * 132 + k8 + tig];
            uint32_t a1 = band_sm[(gid + 8) * 132 + k8 + tig];
            uint32_t a2 = band_sm[gid * 132 + k8 + tig + 4];
            uint32_t a3 = band_sm[(gid + 8) * 132 + k8 + tig + 4];
            uint32_t b0 = fcw[(k8 + tig) * 136 + n0 + gid];
            uint32_t b1 = fcw[(k8 + tig + 4) * 136 + n0 + gid];
            mma_tf32(c, a0, a1, a2, a3, b0, b1);
        }
        int d = n0 + tig * 2;
        float2 bias = *(const float2*)&fc_b[d];
        float2 o0, o1;
        o0.x = fmaxf(c[0] + bias.x, 0.f);
        o0.y = fmaxf(c[1] + bias.y, 0.f);
        o1.x = fmaxf(c[2] + bias.x, 0.f);
        o1.y = fmaxf(c[3] + bias.y, 0.f);
        *(float2*)&out[(gt0 + gid) * DD + d]     = o0;
        *(float2*)&out[(gt0 + gid + 8) * DD + d] = o1;
    }
}

// ---------------------------------------------------------------------------
extern "C" void kernel_launch(void* const* d_in, const int* in_sizes, int n_in,
                              void* d_out, int out_size) {
    const float* x0     = (const float*)d_in[0];
    const float* x1     = (const float*)d_in[1];
    const float* proj_w = (const float*)d_in[2];
    const float* fc_w   = (const float*)d_in[3];
    const float* fc_b   = (const float*)d_in[4];
    float* out = (float*)d_out;

    cudaFuncSetAttribute(bandfc_kernel,
                         cudaFuncAttributeMaxDynamicSharedMemorySize,
                         BFC_SMEM_BYTES);

    pool_kernel<<<2048, 32>>>(x0, x1);
    gemm_proj_kernel<<<dim3(64, KSPLIT), 256>>>(proj_w);
    norm_kernel<<<512, 128>>>(fc_w);
    bandfc_kernel<<<128, 512, BFC_SMEM_BYTES>>>(fc_b, out);
}

// round 16
// speedup vs baseline: 1.4924x; 1.0472x over previous
#include <cuda_runtime.h>
#include <cstdint>

// Problem constants
#define BB 2
#define C0 512
#define CT 1024        // total channels
#define TT 1024        // time
#define HW 49          // 7*7
#define DD 128         // SIM_DIM / OUT_DIM
#define LL 101         // LOOKUP
#define W2 50

#define KSPLIT 8

// Scratch (device globals: allowed; no runtime allocation)
__device__ uint32_t g_feats[BB * CT * TT];            // [b][c][t] tf32 bits, 8 MB
__device__ uint32_t g_projw32[CT * DD];               // proj_w tf32, dense [c][d]
__device__ float g_xpart[KSPLIT][BB * TT * DD];       // k-split partials (fp32)
__device__ uint32_t g_xnorm[BB * TT * DD];            // normalized rows, tf32 bits
__device__ uint32_t g_fcw32[104 * 136];               // fc_w as tf32, prepadded

// ---- tf32 / mma helpers ----------------------------------------------------
__device__ __forceinline__ uint32_t f2tf32(float x) {
    uint32_t r;
    asm("cvt.rna.tf32.f32 %0, %1;" : "=r"(r) : "f"(x));
    return r;
}
__device__ __forceinline__ void mma_tf32(float c[4], uint32_t a0, uint32_t a1,
                                         uint32_t a2, uint32_t a3,
                                         uint32_t b0, uint32_t b1) {
    asm("mma.sync.aligned.m16n8k8.row.col.f32.tf32.tf32.f32 "
        "{%0,%1,%2,%3}, {%4,%5,%6,%7}, {%8,%9}, {%0,%1,%2,%3};"
        : "+f"(c[0]), "+f"(c[1]), "+f"(c[2]), "+f"(c[3])
        : "r"(a0), "r"(a1), "r"(a2), "r"(a3), "r"(b0), "r"(b1));
}

// ---- cp.async helpers ------------------------------------------------------
__device__ __forceinline__ void cpasync16(uint32_t s, const void* g) {
    asm volatile("cp.async.cg.shared.global [%0], [%1], 16;" :: "r"(s), "l"(g));
}
__device__ __forceinline__ void cp_commit() {
    asm volatile("cp.async.commit_group;");
}
template <int N> __device__ __forceinline__ void cp_wait() {
    asm volatile("cp.async.wait_group %0;" :: "n"(N));
}

// ---------------------------------------------------------------------------
// K1: spatial mean pool — channel-streaming warps + cp.async double buffering.
// Output stored as tf32 bits (gemm consumed tf32 anyway — identical numerics).
// Also converts proj_w -> g_projw32 (2 words per thread).
// ---------------------------------------------------------------------------
__global__ void __launch_bounds__(32) pool_kernel(const float* __restrict__ x0,
                                                  const float* __restrict__ x1,
                                                  const float* __restrict__ proj_w) {
    __shared__ float sm[2][1568];
    const int lane = threadIdx.x;
    const int ch = blockIdx.x;             // 0..2047
    const int b = ch >> 10;
    const int c = ch & 1023;

    // proj_w -> tf32 (65536 threads, 131072 words: 2 each)
    {
        int gidx = blockIdx.x * 32 + lane;
        g_projw32[gidx] = f2tf32(proj_w[gidx]);
        g_projw32[gidx + 65536] = f2tf32(proj_w[gidx + 65536]);
    }

    const float* src = (c < C0)
        ? x0 + (size_t)(b * C0 + c) * TT * HW
        : x1 + (size_t)(b * C0 + (c - C0)) * TT * HW;

    uint32_t sb[2];
    sb[0] = (uint32_t)__cvta_generic_to_shared(&sm[0][0]);
    sb[1] = (uint32_t)__cvta_generic_to_shared(&sm[1][0]);

    auto issue = [&](int k, int buf) {
        const float4* g = (const float4*)(src + (size_t)k * 1568);
        uint32_t s = sb[buf];
#pragma unroll
        for (int i = 0; i < 12; i++)
            cpasync16(s + (i * 32 + lane) * 16, g + i * 32 + lane);
        if (lane < 8)
            cpasync16(s + (384 + lane) * 16, g + 384 + lane);
        cp_commit();
    };

    issue(0, 0);
    issue(1, 1);

    uint32_t* dst = &g_feats[(size_t)ch * TT];

    for (int k = 0; k < 32; k++) {
        if (k < 31) cp_wait<1>(); else cp_wait<0>();
        __syncwarp();
        const float* row = &sm[k & 1][lane * 49];
        float s = 0.f;
#pragma unroll
        for (int j = 0; j < 49; j++) s += row[j];
        dst[k * 32 + lane] = f2tf32(s * (1.0f / 49.0f));
        __syncwarp();
        if (k + 2 < 32) issue(k + 2, k & 1);
    }
}

// ---------------------------------------------------------------------------
// K2: projection GEMM, TF32 mma, pure cp.async staging.
// Block: M=64 x N=128 x K=128, 512 threads (16 warps = 4 m16 x 4 n32).
// KSPLIT=8 -> grid (32,8)=256 blocks, 2 blocks/SM (106.5 KB dyn smem).
// Smem: A [k128][m 72] (banks tig*8+gid), B [k128][n 136] (banks tig*8+n).
// ---------------------------------------------------------------------------
#define GEMM_SMEM_WORDS (128 * 72 + 128 * 136)
#define GEMM_SMEM_BYTES (GEMM_SMEM_WORDS * 4)

__global__ void __launch_bounds__(512) gemm_proj_kernel() {
    extern __shared__ uint32_t gsm[];
    uint32_t* As = gsm;                    // 128 x 72
    uint32_t* Bs = gsm + 128 * 72;         // 128 x 136

    const int tid = threadIdx.x;
    const int gm0 = blockIdx.x * 64;       // global row base (b*T + t)
    const int b = gm0 >> 10;
    const int t0 = gm0 & 1023;
    const int k0 = blockIdx.y * 128;

    const int w = tid >> 5;
    const int lane = tid & 31;
    const int m0 = (w >> 2) * 16;          // 0,16,32,48
    const int n0 = (w & 3) * 32;           // 0,32,64,96
    const int gid = lane >> 2;             // 0..7
    const int tig = lane & 3;              // 0..3

    const uint32_t sm_base = (uint32_t)__cvta_generic_to_shared(gsm);

    // stage A: 128 k-rows x 16 chunks (64 t) = 2048 chunks, 4 per thread
#pragma unroll
    for (int i = 0; i < 4; i++) {
        int idx = tid + i * 512;
        int r = idx >> 4, q = idx & 15;
        cpasync16(sm_base + (r * 72 + q * 4) * 4,
                  &g_feats[(((b << 10) + k0 + r) << 10) + t0 + q * 4]);
    }
    // stage B: 128 k-rows x 32 chunks (128 d) = 4096 chunks, 8 per thread
#pragma unroll
    for (int i = 0; i < 8; i++) {
        int idx = tid + i * 512;
        int r = idx >> 5, q = idx & 31;
        cpasync16(sm_base + (128 * 72 + r * 136 + q * 4) * 4,
                  &g_projw32[((k0 + r) << 7) + q * 4]);
    }
    cp_commit();
    cp_wait<0>();
    __syncthreads();

    float c[4][4];
#pragma unroll
    for (int i = 0; i < 4; i++)
#pragma unroll
        for (int j = 0; j < 4; j++) c[i][j] = 0.f;

#pragma unroll
    for (int k8 = 0; k8 < 128; k8 += 8) {
        uint32_t a0 = As[(k8 + tig) * 72 + m0 + gid];
        uint32_t a1 = As[(k8 + tig) * 72 + m0 + gid + 8];
        uint32_t a2 = As[(k8 + tig + 4) * 72 + m0 + gid];
        uint32_t a3 = As[(k8 + tig + 4) * 72 + m0 + gid + 8];
#pragma unroll
        for (int nf = 0; nf < 4; nf++) {
            int n = n0 + nf * 8 + gid;
            uint32_t b0 = Bs[(k8 + tig) * 136 + n];
            uint32_t b1 = Bs[(k8 + tig + 4) * 136 + n];
            mma_tf32(c[nf], a0, a1, a2, a3, b0, b1);
        }
    }

    float* dst = g_xpart[blockIdx.y];
#pragma unroll
    for (int nf = 0; nf < 4; nf++) {
        int col = n0 + nf * 8 + tig * 2;
        *(float2*)&dst[(gm0 + m0 + gid) * DD + col]     = make_float2(c[nf][0], c[nf][1]);
        *(float2*)&dst[(gm0 + m0 + gid + 8) * DD + col] = make_float2(c[nf][2], c[nf][3]);
    }
}

// ---------------------------------------------------------------------------
// K3: sum KSPLIT partials, L2-normalize, store as TF32 bits.  Warp per row.
// Also converts fc_w into prepadded tf32 g_fcw32 (spare thread capacity).
// ---------------------------------------------------------------------------
__global__ void __launch_bounds__(128) norm_kernel(const float* __restrict__ fc_w) {
    // fc_w -> g_fcw32 [k 104][d 136], rows >= 101 and cols >= 128 zero
    {
        int gidx = blockIdx.x * 128 + threadIdx.x;     // 65536 threads >= 14144
        if (gidx < 104 * 136) {
            int k = gidx / 136, d = gidx - k * 136;
            uint32_t v = 0u;
            if (k < LL && d < DD) v = f2tf32(fc_w[k * DD + d]);
            g_fcw32[gidx] = v;
        }
    }

    const int row = blockIdx.x * 4 + (threadIdx.x >> 5);   // 0..2047
    const int lane = threadIdx.x & 31;
    float4 v = make_float4(0.f, 0.f, 0.f, 0.f);
#pragma unroll
    for (int s = 0; s < KSPLIT; s++) {
        float4 p = ((const float4*)g_xpart[s])[row * 32 + lane];
        v.x += p.x; v.y += p.y; v.z += p.z; v.w += p.w;
    }
    float sq = v.x * v.x + v.y * v.y + v.z * v.z + v.w * v.w;
#pragma unroll
    for (int o = 16; o; o >>= 1) sq += __shfl_xor_sync(0xFFFFFFFFu, sq, o);
    const float inv = 1.0f / fmaxf(sqrtf(sq), 1e-12f);
    uint4 o;
    o.x = f2tf32(v.x * inv); o.y = f2tf32(v.y * inv);
    o.z = f2tf32(v.z * inv); o.w = f2tf32(v.w * inv);
    ((uint4*)g_xnorm)[row * 32 + lane] = o;
}

// ---------------------------------------------------------------------------
// K4: fused banded similarity + fc on TF32 tensor cores, cp.async staging.
// Window in commit group 0, fcw in group 1 -> sim MMA overlaps the fcw fetch.
// Smem: Bsm 128*132 | fcw 104*136 | band 16*132 = 129.5 KB.
// ---------------------------------------------------------------------------
#define BFC_SMEM_WORDS (128 * 132 + 104 * 136 + 16 * 132)
#define BFC_SMEM_BYTES (BFC_SMEM_WORDS * 4)

__global__ void __launch_bounds__(512) bandfc_kernel(const float* __restrict__ fc_b,
                                                     float* __restrict__ out) {
    extern __shared__ uint32_t dyn_sm[];
    uint32_t* Bsm = dyn_sm;                        // 128 x 132 tf32
    uint32_t* fcw = Bsm + 128 * 132;               // 104 x 136 tf32 [k][d]
    uint32_t* band_sm = fcw + 104 * 136;           // 16 x 132 tf32 [tl][j]
    uint32_t* Asm = Bsm + W2 * 132;                // A rows = B rows 50..65

    const int tid = threadIdx.x;
    const int gt0 = blockIdx.x * 16;
    const int b = gt0 >> 10;
    const int t0 = gt0 & 1023;
    const int sbase = t0 - W2;             // global s of B row 0

    const int w = tid >> 5;                // warp 0..15
    const int lane = tid & 31;
    const int gid = lane >> 2;             // 0..7
    const int tig = lane & 3;              // 0..3

    const uint32_t sm_base = (uint32_t)__cvta_generic_to_shared(dyn_sm);

    // ---- phase 1: stage via cp.async, two commit groups ----
    // group 0: B window (128 rows x 32 chunks; STS zeros for OOB rows)
#pragma unroll
    for (int i = 0; i < 8; i++) {
        int idx = tid + i * 512;
        int r = idx >> 5, q = idx & 31;
        int s = sbase + r;
        uint32_t dst_off = (r * 132 + q * 4) * 4;
        if (s >= 0 && s < TT) {
            cpasync16(sm_base + dst_off, &g_xnorm[(((b << 10) + s) << 7) + q * 4]);
        } else {
            *(float4*)((char*)dyn_sm + dst_off) = make_float4(0.f, 0.f, 0.f, 0.f);
        }
    }
    cp_commit();
    // group 1: fcw linear copy (3536 chunks)
    {
        const uint32_t fcw_off = 128 * 132 * 4;
        for (int i = tid; i < 3536; i += 512)
            cpasync16(sm_base + fcw_off + i * 16, &g_fcw32[i * 4]);
    }
    cp_commit();
    // band k-pad cols 101..103 (16 x 3)
    if (tid < 48) {
        int tl = tid / 3, kk = LL + tid % 3;
        band_sm[tl * 132 + kk] = 0u;
    }
    cp_wait<1>();                          // window ready; fcw may still fly
    __syncthreads();

    // ---- phase 2: sim MMA + scatter (as tf32) ----
    {
        float acc[4] = {0.f, 0.f, 0.f, 0.f};
        const int nrow = w * 8 + gid;
#pragma unroll
        for (int k8 = 0; k8 < 128; k8 += 8) {
            uint32_t a0 = Asm[gid * 132 + k8 + tig];
            uint32_t a1 = Asm[(gid + 8) * 132 + k8 + tig];
            uint32_t a2 = Asm[gid * 132 + k8 + tig + 4];
            uint32_t a3 = Asm[(gid + 8) * 132 + k8 + tig + 4];
            uint32_t b0 = Bsm[nrow * 132 + k8 + tig];
            uint32_t b1 = Bsm[nrow * 132 + k8 + tig + 4];
            mma_tf32(acc, a0, a1, a2, a3, b0, b1);
        }
        int scol = w * 8 + tig * 2;
#pragma unroll
        for (int h = 0; h < 2; h++) {
            int tl = gid + h * 8;
            int j0 = scol - tl;
            if (j0 >= 0 && j0 <= 100) band_sm[tl * 132 + j0] = f2tf32(acc[h * 2 + 0]);
            if (j0 + 1 >= 0 && j0 + 1 <= 100) band_sm[tl * 132 + j0 + 1] = f2tf32(acc[h * 2 + 1]);
        }
    }
    cp_wait<0>();                          // fcw landed
    __syncthreads();

    // ---- phase 3: fc MMA (m16 x n128 x k104) + bias + relu ----
    {
        float c[4] = {0.f, 0.f, 0.f, 0.f};
        const int n0 = w * 8;
#pragma unroll
        for (int k8 = 0; k8 < 104; k8 += 8) {
            uint32_t a0 = band_sm[gid * 132 + k8 + tig];
            uint32_t a1 = band_sm[(gid + 8) * 132 + k8 + tig];
            uint32_t a2 = band_sm[gid * 132 + k8 + tig + 4];
            uint32_t a3 = band_sm[(gid + 8) * 132 + k8 + tig + 4];
            uint32_t b0 = fcw[(k8 + tig) * 136 + n0 + gid];
            uint32_t b1 = fcw[(k8 + tig + 4) * 136 + n0 + gid];
            mma_tf32(c, a0, a1, a2, a3, b0, b1);
        }
        int d = n0 + tig * 2;
        float2 bias = *(const float2*)&fc_b[d];
        float2 o0, o1;
        o0.x = fmaxf(c[0] + bias.x, 0.f);
        o0.y = fmaxf(c[1] + bias.y, 0.f);
        o1.x = fmaxf(c[2] + bias.x, 0.f);
        o1.y = fmaxf(c[3] + bias.y, 0.f);
        *(float2*)&out[(gt0 + gid) * DD + d]     = o0;
        *(float2*)&out[(gt0 + gid + 8) * DD + d] = o1;
    }
}

// ---------------------------------------------------------------------------
extern "C" void kernel_launch(void* const* d_in, const int* in_sizes, int n_in,
                              void* d_out, int out_size) {
    const float* x0     = (const float*)d_in[0];
    const float* x1     = (const float*)d_in[1];
    const float* proj_w = (const float*)d_in[2];
    const float* fc_w   = (const float*)d_in[3];
    const float* fc_b   = (const float*)d_in[4];
    float* out = (float*)d_out;

    cudaFuncSetAttribute(gemm_proj_kernel,
                         cudaFuncAttributeMaxDynamicSharedMemorySize,
                         GEMM_SMEM_BYTES);
    cudaFuncSetAttribute(bandfc_kernel,
                         cudaFuncAttributeMaxDynamicSharedMemorySize,
                         BFC_SMEM_BYTES);

    pool_kernel<<<2048, 32>>>(x0, x1, proj_w);
    gemm_proj_kernel<<<dim3(32, KSPLIT), 512, GEMM_SMEM_BYTES>>>();
    norm_kernel<<<512, 128>>>(fc_w);
    bandfc_kernel<<<128, 512, BFC_SMEM_BYTES>>>(fc_b, out);
}